// round 7
// baseline (speedup 1.0000x reference)
#include <cuda_runtime.h>
#include <cstdint>
#include <math.h>

// ---------------------------------------------------------------- constants
#define D_IN    2048
#define HEADS   16
#define GROUPS  2
#define HD      128
#define BATCH   8
#define SEQ     512
#define CACHE   256
#define T_TOT   768
#define M_ROWS  (BATCH*SEQ)                 // 4096
#define QKV_N   2560
#define OUT_O_SIZE (M_ROWS*D_IN)
#define OUT_K_SIZE (BATCH*T_TOT*GROUPS*HD)

// ---------------------------------------------------------------- scratch
__device__ float g_qkv[M_ROWS * QKV_N];
__device__ float g_q[M_ROWS * D_IN];             // roped+scaled q (b,h,s,hd)
__device__ float g_attn[M_ROWS * D_IN];
__device__ float g_wT[QKV_N * D_IN];             // combined [n_qkv][2048]
__device__ float g_woT[D_IN * D_IN];             // [n][2048]
__device__ float g_vT[16 * HD * T_TOT];          // per bg: [hd][768]
__device__ float g_bias[QKV_N];

// ---------------------------------------------------------------- helpers
__device__ __forceinline__ uint32_t smem_u32(const void* p) {
    uint32_t a;
    asm("{ .reg .u64 t; cvta.to.shared.u64 t, %1; cvt.u32.u64 %0, t; }" : "=r"(a) : "l"(p));
    return a;
}
__device__ __forceinline__ uint32_t f2tf32(float f) {
    uint32_t r;
    asm("cvt.rna.tf32.f32 %0, %1;" : "=r"(r) : "f"(f));
    return r;
}
__device__ __forceinline__ void mma_tf32(float c[4],
                                         uint32_t a0, uint32_t a1, uint32_t a2, uint32_t a3,
                                         uint32_t b0, uint32_t b1) {
    asm volatile(
        "mma.sync.aligned.m16n8k8.row.col.f32.tf32.tf32.f32 "
        "{%0,%1,%2,%3}, {%4,%5,%6,%7}, {%8,%9}, {%0,%1,%2,%3};"
        : "+f"(c[0]), "+f"(c[1]), "+f"(c[2]), "+f"(c[3])
        : "r"(a0), "r"(a1), "r"(a2), "r"(a3), "r"(b0), "r"(b1));
}

#define CP_ASYNC16(dst, src) \
    asm volatile("cp.async.cg.shared.global [%0], [%1], 16;" :: "r"(dst), "l"(src) : "memory")
#define CP_COMMIT() asm volatile("cp.async.commit_group;" ::: "memory")
#define CP_WAIT2()  asm volatile("cp.async.wait_group 2;" ::: "memory")
#define CP_WAIT1()  asm volatile("cp.async.wait_group 1;" ::: "memory")
#define CP_WAIT0()  asm volatile("cp.async.wait_group 0;" ::: "memory")

// ---------------------------------------------------------------- GEMM core (projections)
// CTA tile 128x128, K chunk 32, 256 threads = 8 warps (4m x 2n), warp 32x64.
#define SROW 36
#define STAGE_FLOATS (2 * 128 * SROW)
#define NSTAGE 3
#define GEMM_SMEM_BYTES (NSTAGE * STAGE_FLOATS * 4)  // 110592

__device__ __forceinline__ void mma_gemm(
    const float* __restrict__ A, int lda,
    const float* __restrict__ B, int ldb,
    int n_chunks, float* sm, float c[2][8][4])
{
    const int tid  = threadIdx.x;
    const int lane = tid & 31;
    const int wid  = tid >> 5;
    const int wm   = wid >> 1;
    const int wn   = wid & 1;
    const uint32_t sbase = smem_u32(sm);

    const int srow0 = tid >> 3;
    const int sc16  = (tid & 7);

    #pragma unroll
    for (int mt = 0; mt < 2; mt++)
        #pragma unroll
        for (int nt = 0; nt < 8; nt++)
            #pragma unroll
            for (int q = 0; q < 4; q++) c[mt][nt][q] = 0.f;

    auto issue = [&](int chunk, int stage) {
        if (chunk < n_chunks) {
            uint32_t sA = sbase + stage * (STAGE_FLOATS * 4);
            uint32_t sB = sA + 128 * SROW * 4;
            #pragma unroll
            for (int it = 0; it < 4; it++) {
                int row = srow0 + it * 32;
                const float* ap = A + (size_t)row * lda + chunk * 32 + sc16 * 4;
                CP_ASYNC16(sA + row * (SROW * 4) + sc16 * 16, ap);
                const float* bp = B + (size_t)row * ldb + chunk * 32 + sc16 * 4;
                CP_ASYNC16(sB + row * (SROW * 4) + sc16 * 16, bp);
            }
        }
        CP_COMMIT();
    };

    auto compute = [&](int s) {
        const float* As = sm + s * STAGE_FLOATS;
        const float* Bs = As + 128 * SROW;
        const float* ap = As + (wm * 32 + (lane >> 2)) * SROW + (lane & 3);
        const float* bp = Bs + (wn * 64 + (lane >> 2)) * SROW + (lane & 3);
        #pragma unroll
        for (int ks = 0; ks < 4; ks++) {
            uint32_t af[2][4];
            #pragma unroll
            for (int mt = 0; mt < 2; mt++) {
                const float* p = ap + mt * 16 * SROW + ks * 8;
                af[mt][0] = f2tf32(p[0]);
                af[mt][1] = f2tf32(p[8 * SROW]);
                af[mt][2] = f2tf32(p[4]);
                af[mt][3] = f2tf32(p[8 * SROW + 4]);
            }
            #pragma unroll
            for (int nt = 0; nt < 8; nt++) {
                const float* p = bp + nt * 8 * SROW + ks * 8;
                uint32_t b0 = f2tf32(p[0]), b1 = f2tf32(p[4]);
                #pragma unroll
                for (int mt = 0; mt < 2; mt++)
                    mma_tf32(c[mt][nt], af[mt][0], af[mt][1], af[mt][2], af[mt][3], b0, b1);
            }
        }
    };

    issue(0, 0);
    issue(1, 1);
    for (int i = 0; i < n_chunks; i++) {
        issue(i + 2, (i + 2) % NSTAGE);
        CP_WAIT2();
        __syncthreads();
        compute(i % NSTAGE);
        __syncthreads();
    }
}

#define EPI_ROW(mt, half)  (( (threadIdx.x >> 6) & 3 ) * 32 + (mt) * 16 + ((threadIdx.x & 31) >> 2) + (half) * 8)
#define EPI_COL(nt)        (( (threadIdx.x >> 5) & 1 ) * 64 + (nt) * 8 + ((threadIdx.x & 31) & 3) * 2)

// ---------------------------------------------------------------- projection kernels

__global__ void __launch_bounds__(256, 2) qkv_gemm_kernel(const float* __restrict__ x)
{
    extern __shared__ float sm[];
    int row0 = blockIdx.x * 128;
    int n0 = blockIdx.y * 128;

    float c[2][8][4];
    mma_gemm(x + (size_t)row0 * D_IN, D_IN, g_wT + (size_t)n0 * D_IN, D_IN,
             D_IN / 32, sm, c);

    #pragma unroll
    for (int mt = 0; mt < 2; mt++)
        #pragma unroll
        for (int half = 0; half < 2; half++) {
            int r = row0 + EPI_ROW(mt, half);
            #pragma unroll
            for (int nt = 0; nt < 8; nt++) {
                int cl = EPI_COL(nt);
                float2 v;
                v.x = c[mt][nt][half*2+0] + g_bias[n0 + cl];
                v.y = c[mt][nt][half*2+1] + g_bias[n0 + cl + 1];
                *(float2*)&g_qkv[(size_t)r * QKV_N + n0 + cl] = v;
            }
        }
}

__global__ void __launch_bounds__(256, 2) outproj_gemm_kernel(
    const float* __restrict__ bo, float* __restrict__ out_o)
{
    extern __shared__ float sm[];
    int row0 = blockIdx.x * 128;
    int n0 = blockIdx.y * 128;

    float c[2][8][4];
    mma_gemm(g_attn + (size_t)row0 * D_IN, D_IN, g_woT + (size_t)n0 * D_IN, D_IN,
             D_IN / 32, sm, c);

    #pragma unroll
    for (int mt = 0; mt < 2; mt++)
        #pragma unroll
        for (int half = 0; half < 2; half++) {
            int r = row0 + EPI_ROW(mt, half);
            #pragma unroll
            for (int nt = 0; nt < 8; nt++) {
                int cl = EPI_COL(nt);
                float2 v;
                v.x = c[mt][nt][half*2+0] + bo[n0 + cl];
                v.y = c[mt][nt][half*2+1] + bo[n0 + cl + 1];
                *(float2*)&out_o[(size_t)r * D_IN + n0 + cl] = v;
            }
        }
}

// ---------------------------------------------------------------- fused flash attention
// CTA: one (b,h) x 128 q-rows. smem: Q[128][132] + KP[128][132] + V[128][132] + red[512].
#define SROWF 132
#define FLASH_SMEM_FLOATS (3 * 128 * SROWF + 512)
#define FLASH_SMEM_BYTES (FLASH_SMEM_FLOATS * 4)     // 204800

__global__ void __launch_bounds__(256, 1) flash_attn_kernel(const float* __restrict__ kbase)
{
    extern __shared__ float sm[];
    float* Qs = sm;
    float* KP = sm + 128 * SROWF;
    float* Vs = sm + 2 * 128 * SROWF;
    float* redmax = sm + 3 * 128 * SROWF;    // [2][128]
    float* redsum = redmax + 256;            // [2][128]

    const int tid = threadIdx.x;
    const int lane = tid & 31;
    const int wid = tid >> 5;
    const int wm = wid >> 1;       // 0..3
    const int wn = wid & 1;        // 0..1

    const int bh = blockIdx.y;
    const int b = bh >> 4, h = bh & 15, g = h >> 3;
    const int bg = b * 2 + g;
    const int s0 = blockIdx.x * 128;

    const uint32_t sbase = smem_u32(sm);
    const uint32_t qb = sbase;
    const uint32_t kpb = sbase + 128 * SROWF * 4;
    const uint32_t vb = sbase + 2 * 128 * SROWF * 4;

    // staging: 2 threads per row, 64 floats (16 x 16B) per thread
    const int srow = tid >> 1;           // 0..127
    const int scb  = (tid & 1) * 64;     // float col base: 0 or 64

    // stage Q (group 0)
    {
        const float* qsrc = g_q + (((size_t)b * HEADS + h) * SEQ + s0) * HD;
        #pragma unroll
        for (int q = 0; q < 16; q++)
            CP_ASYNC16(qb + (srow * SROWF + scb + q * 4) * 4,
                       qsrc + (size_t)srow * HD + scb + q * 4);
        CP_COMMIT();
    }

    const float* kptr = kbase + ((size_t)b * T_TOT * GROUPS + g) * HD;  // row t, stride 256
    const float* vptr = g_vT + (size_t)bg * HD * T_TOT;                 // row hd, stride 768

    float m_[2][2], l_[2][2], co[2][8][4];
    #pragma unroll
    for (int mt = 0; mt < 2; mt++)
        #pragma unroll
        for (int half = 0; half < 2; half++) { m_[mt][half] = -1e30f; l_[mt][half] = 0.f; }
    #pragma unroll
    for (int mt = 0; mt < 2; mt++)
        #pragma unroll
        for (int nt = 0; nt < 8; nt++)
            #pragma unroll
            for (int q = 0; q < 4; q++) co[mt][nt][q] = 0.f;

    const float* ap = Qs + (wm * 32 + (lane >> 2)) * SROWF + (lane & 3);
    const float* bpK = KP + (wn * 64 + (lane >> 2)) * SROWF + (lane & 3);
    const float* bpV = Vs + (wn * 64 + (lane >> 2)) * SROWF + (lane & 3);

    int myrow[2][2];
    #pragma unroll
    for (int mt = 0; mt < 2; mt++)
        #pragma unroll
        for (int half = 0; half < 2; half++)
            myrow[mt][half] = wm * 32 + mt * 16 + (lane >> 2) + half * 8;

    for (int tc = 0; tc < T_TOT / 128; tc++) {
        const int t0 = tc * 128;
        // stage K (one group), then V (one group)
        #pragma unroll
        for (int q = 0; q < 16; q++)
            CP_ASYNC16(kpb + (srow * SROWF + scb + q * 4) * 4,
                       kptr + (size_t)(t0 + srow) * (GROUPS * HD) + scb + q * 4);
        CP_COMMIT();
        #pragma unroll
        for (int q = 0; q < 16; q++)
            CP_ASYNC16(vb + (srow * SROWF + scb + q * 4) * 4,
                       vptr + (size_t)srow * T_TOT + t0 + scb + q * 4);
        CP_COMMIT();
        CP_WAIT1();          // Q + K ready; V may lag
        __syncthreads();

        // ---- S = Q @ K^T  (128x128, 16 k-steps of 8)
        float cs[2][8][4];
        #pragma unroll
        for (int mt = 0; mt < 2; mt++)
            #pragma unroll
            for (int nt = 0; nt < 8; nt++)
                #pragma unroll
                for (int q = 0; q < 4; q++) cs[mt][nt][q] = 0.f;

        #pragma unroll
        for (int ks = 0; ks < 16; ks++) {
            uint32_t af[2][4];
            #pragma unroll
            for (int mt = 0; mt < 2; mt++) {
                const float* p = ap + mt * 16 * SROWF + ks * 8;
                af[mt][0] = f2tf32(p[0]);
                af[mt][1] = f2tf32(p[8 * SROWF]);
                af[mt][2] = f2tf32(p[4]);
                af[mt][3] = f2tf32(p[8 * SROWF + 4]);
            }
            #pragma unroll
            for (int nt = 0; nt < 8; nt++) {
                const float* p = bpK + nt * 8 * SROWF + ks * 8;
                uint32_t b0 = f2tf32(p[0]), b1 = f2tf32(p[4]);
                #pragma unroll
                for (int mt = 0; mt < 2; mt++)
                    mma_tf32(cs[mt][nt], af[mt][0], af[mt][1], af[mt][2], af[mt][3], b0, b1);
            }
        }

        // ---- online softmax: row max (quad shuffle + cross-warp smem)
        #pragma unroll
        for (int mt = 0; mt < 2; mt++)
            #pragma unroll
            for (int half = 0; half < 2; half++) {
                float mx = -1e30f;
                #pragma unroll
                for (int nt = 0; nt < 8; nt++)
                    mx = fmaxf(mx, fmaxf(cs[mt][nt][half*2], cs[mt][nt][half*2+1]));
                mx = fmaxf(mx, __shfl_xor_sync(0xffffffffu, mx, 1));
                mx = fmaxf(mx, __shfl_xor_sync(0xffffffffu, mx, 2));
                if ((lane & 3) == 0) redmax[wn * 128 + myrow[mt][half]] = mx;
            }
        __syncthreads();   // also: all warps done reading K from KP

        float sc[2][2];
        #pragma unroll
        for (int mt = 0; mt < 2; mt++)
            #pragma unroll
            for (int half = 0; half < 2; half++) {
                int r = myrow[mt][half];
                float mnew = fmaxf(m_[mt][half], fmaxf(redmax[r], redmax[128 + r]));
                sc[mt][half] = __expf(m_[mt][half] - mnew);
                m_[mt][half] = mnew;
            }

        // exp, partial sums, write P into KP
        #pragma unroll
        for (int mt = 0; mt < 2; mt++)
            #pragma unroll
            for (int half = 0; half < 2; half++) {
                int r = myrow[mt][half];
                float mnew = m_[mt][half];
                float sum = 0.f;
                float* prow = KP + r * SROWF + wn * 64 + (lane & 3) * 2;
                #pragma unroll
                for (int nt = 0; nt < 8; nt++) {
                    float p0 = __expf(cs[mt][nt][half*2+0] - mnew);
                    float p1 = __expf(cs[mt][nt][half*2+1] - mnew);
                    sum += p0 + p1;
                    *(float2*)&prow[nt * 8] = make_float2(p0, p1);
                }
                sum += __shfl_xor_sync(0xffffffffu, sum, 1);
                sum += __shfl_xor_sync(0xffffffffu, sum, 2);
                if ((lane & 3) == 0) redsum[wn * 128 + r] = sum;
            }
        CP_WAIT0();        // this thread's V copies done
        __syncthreads();   // P + redsum + everyone's V visible

        #pragma unroll
        for (int mt = 0; mt < 2; mt++)
            #pragma unroll
            for (int half = 0; half < 2; half++) {
                int r = myrow[mt][half];
                l_[mt][half] = l_[mt][half] * sc[mt][half] + redsum[r] + redsum[128 + r];
                #pragma unroll
                for (int nt = 0; nt < 8; nt++) {
                    co[mt][nt][half*2+0] *= sc[mt][half];
                    co[mt][nt][half*2+1] *= sc[mt][half];
                }
            }

        // ---- O += P @ V^T   (A = P in KP, B = Vs[hd][t])
        const float* ap2 = KP + (wm * 32 + (lane >> 2)) * SROWF + (lane & 3);
        #pragma unroll
        for (int ks = 0; ks < 16; ks++) {
            uint32_t af[2][4];
            #pragma unroll
            for (int mt = 0; mt < 2; mt++) {
                const float* p = ap2 + mt * 16 * SROWF + ks * 8;
                af[mt][0] = f2tf32(p[0]);
                af[mt][1] = f2tf32(p[8 * SROWF]);
                af[mt][2] = f2tf32(p[4]);
                af[mt][3] = f2tf32(p[8 * SROWF + 4]);
            }
            #pragma unroll
            for (int nt = 0; nt < 8; nt++) {
                const float* p = bpV + nt * 8 * SROWF + ks * 8;
                uint32_t b0 = f2tf32(p[0]), b1 = f2tf32(p[4]);
                #pragma unroll
                for (int mt = 0; mt < 2; mt++)
                    mma_tf32(co[mt][nt], af[mt][0], af[mt][1], af[mt][2], af[mt][3], b0, b1);
            }
        }
        __syncthreads();   // PV done before next chunk overwrites KP/Vs
    }

    // ---- epilogue: normalize, write g_attn (b,s,h*hd)
    #pragma unroll
    for (int mt = 0; mt < 2; mt++)
        #pragma unroll
        for (int half = 0; half < 2; half++) {
            int r = myrow[mt][half];
            float inv = 1.f / l_[mt][half];
            float* dst = g_attn + ((size_t)b * SEQ + s0 + r) * D_IN + h * HD
                         + wn * 64 + (lane & 3) * 2;
            #pragma unroll
            for (int nt = 0; nt < 8; nt++) {
                float2 v = make_float2(co[mt][nt][half*2+0] * inv,
                                       co[mt][nt][half*2+1] * inv);
                *(float2*)&dst[nt * 8] = v;
            }
        }
}

// ---------------------------------------------------------------- prep kernels
__global__ void transpose_kernel(const float* __restrict__ src, float* __restrict__ dst,
                                 int K, int N)
{
    __shared__ float t[32][33];
    int n0 = blockIdx.x * 32, k0 = blockIdx.y * 32;
    int tx = threadIdx.x, ty = threadIdx.y;   // 32 x 8
    #pragma unroll
    for (int j = 0; j < 32; j += 8)
        t[ty + j][tx] = src[(size_t)(k0 + ty + j) * N + n0 + tx];
    __syncthreads();
    #pragma unroll
    for (int j = 0; j < 32; j += 8)
        dst[(size_t)(n0 + ty + j) * K + k0 + tx] = t[tx][ty + j];
}

__global__ void bias_combine_kernel(const float* __restrict__ bq,
                                    const float* __restrict__ bk,
                                    const float* __restrict__ bv)
{
    int i = blockIdx.x * blockDim.x + threadIdx.x;
    if (i >= QKV_N) return;
    float v;
    if (i < 2048) v = bq[i];
    else if (i < 2304) v = bk[i - 2048];
    else v = bv[i - 2304];
    g_bias[i] = v;
}

__global__ void rope_q_kernel()
{
    int idx = blockIdx.x * blockDim.x + threadIdx.x;
    int j = idx & 63;
    int h = (idx >> 6) & 15;
    int m = idx >> 10;
    const float* src = g_qkv + (size_t)m * QKV_N + h * HD;
    float x1 = src[j], x2 = src[j + 64];
    int s = m & 511, b = m >> 9;
    float pos = (float)(CACHE + s);
    float freq = pos * expf(-(float)j * (9.210340371976184f / 64.f));
    float sn, cs; sincosf(freq, &sn, &cs);
    const float SCALE = 0.08838834764831845f;
    float* dst = g_q + (((size_t)b * HEADS + h) * SEQ + s) * HD;
    dst[j]      = (x1 * cs - x2 * sn) * SCALE;
    dst[j + 64] = (x2 * cs + x1 * sn) * SCALE;
}

__global__ void rope_kv_kernel(float* __restrict__ out_k, float* __restrict__ out_v)
{
    int idx = blockIdx.x * blockDim.x + threadIdx.x;
    int j = idx & 63;
    int g = (idx >> 6) & 1;
    int m = idx >> 7;
    const float* ksrc = g_qkv + (size_t)m * QKV_N + 2048 + g * HD;
    const float* vsrc = g_qkv + (size_t)m * QKV_N + 2304 + g * HD;
    float x1 = ksrc[j], x2 = ksrc[j + 64];
    int s = m & 511, b = m >> 9;
    float pos = (float)(CACHE + s);
    float freq = pos * expf(-(float)j * (9.210340371976184f / 64.f));
    float sn, cs; sincosf(freq, &sn, &cs);
    size_t base = (((size_t)b * T_TOT + CACHE + s) * GROUPS + g) * HD;
    out_k[base + j]      = x1 * cs - x2 * sn;
    out_k[base + j + 64] = x2 * cs + x1 * sn;
    out_v[base + j]      = vsrc[j];
    out_v[base + j + 64] = vsrc[j + 64];
}

__global__ void copy_prev_kernel(const float* __restrict__ prev_k,
                                 const float* __restrict__ prev_v,
                                 float* __restrict__ out_k,
                                 float* __restrict__ out_v)
{
    int idx = blockIdx.x * blockDim.x + threadIdx.x;
    if (idx >= BATCH * CACHE * GROUPS * HD) return;
    int b = idx >> 16;
    int r = idx & 65535;
    out_k[(size_t)b * (T_TOT * GROUPS * HD) + r] = prev_k[idx];
    out_v[(size_t)b * (T_TOT * GROUPS * HD) + r] = prev_v[idx];
}

__global__ void vt_prev_kernel(const float* __restrict__ prev_v)
{
    int idx = blockIdx.x * blockDim.x + threadIdx.x;   // 16*128*256
    int t = idx & 255;
    int hd = (idx >> 8) & 127;
    int bg = idx >> 15;
    int b = bg >> 1, g = bg & 1;
    g_vT[(size_t)bg * HD * T_TOT + (size_t)hd * T_TOT + t] =
        prev_v[(((size_t)b * CACHE + t) * GROUPS + g) * HD + hd];
}

__global__ void vt_new_kernel()
{
    int idx = blockIdx.x * blockDim.x + threadIdx.x;   // 16*128*512
    int s = idx & 511;
    int hd = (idx >> 9) & 127;
    int bg = idx >> 16;
    int b = bg >> 1, g = bg & 1;
    g_vT[(size_t)bg * HD * T_TOT + (size_t)hd * T_TOT + CACHE + s] =
        g_qkv[((size_t)b * SEQ + s) * QKV_N + 2304 + g * HD + hd];
}

// ---------------------------------------------------------------- launcher
extern "C" void kernel_launch(void* const* d_in, const int* in_sizes, int n_in,
                              void* d_out, int out_size)
{
    const float* x      = (const float*)d_in[0];
    const float* prev_k = (const float*)d_in[1];
    const float* prev_v = (const float*)d_in[2];
    const float* Wq     = (const float*)d_in[3];
    const float* bq     = (const float*)d_in[4];
    const float* Wk     = (const float*)d_in[5];
    const float* bk     = (const float*)d_in[6];
    const float* Wv     = (const float*)d_in[7];
    const float* bv     = (const float*)d_in[8];
    const float* Wo     = (const float*)d_in[9];
    const float* bo     = (const float*)d_in[10];

    float* out_o = (float*)d_out;
    float* out_k = out_o + OUT_O_SIZE;
    float* out_v = out_k + OUT_K_SIZE;

    static bool attr_set = false;
    if (!attr_set) {
        cudaFuncSetAttribute(qkv_gemm_kernel,     cudaFuncAttributeMaxDynamicSharedMemorySize, GEMM_SMEM_BYTES);
        cudaFuncSetAttribute(outproj_gemm_kernel, cudaFuncAttributeMaxDynamicSharedMemorySize, GEMM_SMEM_BYTES);
        cudaFuncSetAttribute(flash_attn_kernel,   cudaFuncAttributeMaxDynamicSharedMemorySize, FLASH_SMEM_BYTES);
        attr_set = true;
    }

    // 0. Weight transposes + bias combine
    {
        float* wT = nullptr; cudaGetSymbolAddress((void**)&wT, g_wT);
        float* woT = nullptr; cudaGetSymbolAddress((void**)&woT, g_woT);
        dim3 blk(32, 8);
        transpose_kernel<<<dim3(64, 64), blk>>>(Wq, wT, D_IN, D_IN);
        transpose_kernel<<<dim3(8, 64), blk>>>(Wk, wT + 2048 * D_IN, D_IN, 256);
        transpose_kernel<<<dim3(8, 64), blk>>>(Wv, wT + 2304 * D_IN, D_IN, 256);
        transpose_kernel<<<dim3(64, 64), blk>>>(Wo, woT, D_IN, D_IN);
        bias_combine_kernel<<<(QKV_N + 255) / 256, 256>>>(bq, bk, bv);
    }

    // 1. kv-cache history (+ transposed V history)
    copy_prev_kernel<<<2048, 256>>>(prev_k, prev_v, out_k, out_v);
    vt_prev_kernel<<<(16 * 128 * 256) / 256, 256>>>(prev_v);

    // 2. QKV projection
    qkv_gemm_kernel<<<dim3(M_ROWS / 128, QKV_N / 128), 256, GEMM_SMEM_BYTES>>>(x);

    // 3. RoPE q / RoPE k + v copy / transposed V
    rope_q_kernel<<<M_ROWS * HEADS * 64 / 256, 256>>>();
    rope_kv_kernel<<<M_ROWS * GROUPS * 64 / 256, 256>>>(out_k, out_v);
    vt_new_kernel<<<(16 * 128 * 512) / 256, 256>>>();

    // 4. Fused flash attention (scores + softmax + PV)
    flash_attn_kernel<<<dim3(SEQ / 128, BATCH * HEADS), 256, FLASH_SMEM_BYTES>>>(out_k);

    // 5. Output projection
    outproj_gemm_kernel<<<dim3(M_ROWS / 128, D_IN / 128), 256, GEMM_SMEM_BYTES>>>(bo, out_o);
}

// round 8
// speedup vs baseline: 1.0767x; 1.0767x over previous
#include <cuda_runtime.h>
#include <cstdint>
#include <math.h>

// ---------------------------------------------------------------- constants
#define D_IN    2048
#define HEADS   16
#define GROUPS  2
#define HD      128
#define BATCH   8
#define SEQ     512
#define CACHE   256
#define T_TOT   768
#define M_ROWS  (BATCH*SEQ)                 // 4096
#define QKV_N   2560
#define OUT_O_SIZE (M_ROWS*D_IN)
#define OUT_K_SIZE (BATCH*T_TOT*GROUPS*HD)

// ---------------------------------------------------------------- scratch
// All GEMM operands below hold PRE-CONVERTED tf32 bit patterns (in float slots)
__device__ float g_xc[M_ROWS * D_IN];            // x, tf32
__device__ float g_qkv[M_ROWS * QKV_N];          // qkv projection out (fp32)
__device__ float g_q[M_ROWS * D_IN];             // roped+scaled q, tf32
__device__ float g_attn[M_ROWS * D_IN];          // attention out, tf32
__device__ float g_wT[QKV_N * D_IN];             // [n_qkv][2048], tf32
__device__ float g_woT[D_IN * D_IN];             // [n][2048], tf32
__device__ float g_kc[BATCH * T_TOT * GROUPS * HD]; // roped k cache, tf32
__device__ float g_vT[16 * HD * T_TOT];          // per bg: [hd][768], tf32
__device__ float g_bias[QKV_N];

// ---------------------------------------------------------------- helpers
__device__ __forceinline__ uint32_t smem_u32(const void* p) {
    uint32_t a;
    asm("{ .reg .u64 t; cvta.to.shared.u64 t, %1; cvt.u32.u64 %0, t; }" : "=r"(a) : "l"(p));
    return a;
}
__device__ __forceinline__ uint32_t f2tf32(float f) {
    uint32_t r;
    asm("cvt.rna.tf32.f32 %0, %1;" : "=r"(r) : "f"(f));
    return r;
}
__device__ __forceinline__ float f2tf32f(float f) {
    return __uint_as_float(f2tf32(f));
}
__device__ __forceinline__ void mma_tf32(float c[4],
                                         uint32_t a0, uint32_t a1, uint32_t a2, uint32_t a3,
                                         uint32_t b0, uint32_t b1) {
    asm volatile(
        "mma.sync.aligned.m16n8k8.row.col.f32.tf32.tf32.f32 "
        "{%0,%1,%2,%3}, {%4,%5,%6,%7}, {%8,%9}, {%0,%1,%2,%3};"
        : "+f"(c[0]), "+f"(c[1]), "+f"(c[2]), "+f"(c[3])
        : "r"(a0), "r"(a1), "r"(a2), "r"(a3), "r"(b0), "r"(b1));
}

#define CP_ASYNC16(dst, src) \
    asm volatile("cp.async.cg.shared.global [%0], [%1], 16;" :: "r"(dst), "l"(src) : "memory")
#define CP_COMMIT() asm volatile("cp.async.commit_group;" ::: "memory")
#define CP_WAIT2()  asm volatile("cp.async.wait_group 2;" ::: "memory")
#define CP_WAIT1()  asm volatile("cp.async.wait_group 1;" ::: "memory")
#define CP_WAIT0()  asm volatile("cp.async.wait_group 0;" ::: "memory")

// ---------------------------------------------------------------- GEMM core (projections)
// CTA tile 128x128, K chunk 32, 256 threads = 8 warps (4m x 2n), warp 32x64.
// Operands are pre-converted tf32 bits: fragment loads are raw 32-bit LDS.
#define SROW 36
#define STAGE_FLOATS (2 * 128 * SROW)
#define NSTAGE 3
#define GEMM_SMEM_BYTES (NSTAGE * STAGE_FLOATS * 4)  // 110592

__device__ __forceinline__ void mma_gemm(
    const float* __restrict__ A, int lda,
    const float* __restrict__ B, int ldb,
    int n_chunks, float* sm, float c[2][8][4])
{
    const int tid  = threadIdx.x;
    const int lane = tid & 31;
    const int wid  = tid >> 5;
    const int wm   = wid >> 1;
    const int wn   = wid & 1;
    const uint32_t sbase = smem_u32(sm);

    const int srow0 = tid >> 3;
    const int sc16  = (tid & 7);

    #pragma unroll
    for (int mt = 0; mt < 2; mt++)
        #pragma unroll
        for (int nt = 0; nt < 8; nt++)
            #pragma unroll
            for (int q = 0; q < 4; q++) c[mt][nt][q] = 0.f;

    auto issue = [&](int chunk, int stage) {
        if (chunk < n_chunks) {
            uint32_t sA = sbase + stage * (STAGE_FLOATS * 4);
            uint32_t sB = sA + 128 * SROW * 4;
            #pragma unroll
            for (int it = 0; it < 4; it++) {
                int row = srow0 + it * 32;
                const float* ap = A + (size_t)row * lda + chunk * 32 + sc16 * 4;
                CP_ASYNC16(sA + row * (SROW * 4) + sc16 * 16, ap);
                const float* bp = B + (size_t)row * ldb + chunk * 32 + sc16 * 4;
                CP_ASYNC16(sB + row * (SROW * 4) + sc16 * 16, bp);
            }
        }
        CP_COMMIT();
    };

    auto compute = [&](int s) {
        const uint32_t* As = (const uint32_t*)(sm + s * STAGE_FLOATS);
        const uint32_t* Bs = As + 128 * SROW;
        const uint32_t* ap = As + (wm * 32 + (lane >> 2)) * SROW + (lane & 3);
        const uint32_t* bp = Bs + (wn * 64 + (lane >> 2)) * SROW + (lane & 3);
        #pragma unroll
        for (int ks = 0; ks < 4; ks++) {
            uint32_t af[2][4];
            #pragma unroll
            for (int mt = 0; mt < 2; mt++) {
                const uint32_t* p = ap + mt * 16 * SROW + ks * 8;
                af[mt][0] = p[0];
                af[mt][1] = p[8 * SROW];
                af[mt][2] = p[4];
                af[mt][3] = p[8 * SROW + 4];
            }
            #pragma unroll
            for (int nt = 0; nt < 8; nt++) {
                const uint32_t* p = bp + nt * 8 * SROW + ks * 8;
                uint32_t b0 = p[0], b1 = p[4];
                #pragma unroll
                for (int mt = 0; mt < 2; mt++)
                    mma_tf32(c[mt][nt], af[mt][0], af[mt][1], af[mt][2], af[mt][3], b0, b1);
            }
        }
    };

    issue(0, 0);
    issue(1, 1);
    for (int i = 0; i < n_chunks; i++) {
        issue(i + 2, (i + 2) % NSTAGE);
        CP_WAIT2();
        __syncthreads();
        compute(i % NSTAGE);
        __syncthreads();
    }
}

#define EPI_ROW(mt, half)  (( (threadIdx.x >> 6) & 3 ) * 32 + (mt) * 16 + ((threadIdx.x & 31) >> 2) + (half) * 8)
#define EPI_COL(nt)        (( (threadIdx.x >> 5) & 1 ) * 64 + (nt) * 8 + ((threadIdx.x & 31) & 3) * 2)

// ---------------------------------------------------------------- projection kernels

__global__ void __launch_bounds__(256, 2) qkv_gemm_kernel()
{
    extern __shared__ float sm[];
    int row0 = blockIdx.x * 128;
    int n0 = blockIdx.y * 128;

    float c[2][8][4];
    mma_gemm(g_xc + (size_t)row0 * D_IN, D_IN, g_wT + (size_t)n0 * D_IN, D_IN,
             D_IN / 32, sm, c);

    #pragma unroll
    for (int mt = 0; mt < 2; mt++)
        #pragma unroll
        for (int half = 0; half < 2; half++) {
            int r = row0 + EPI_ROW(mt, half);
            #pragma unroll
            for (int nt = 0; nt < 8; nt++) {
                int cl = EPI_COL(nt);
                float2 v;
                v.x = c[mt][nt][half*2+0] + g_bias[n0 + cl];
                v.y = c[mt][nt][half*2+1] + g_bias[n0 + cl + 1];
                *(float2*)&g_qkv[(size_t)r * QKV_N + n0 + cl] = v;
            }
        }
}

__global__ void __launch_bounds__(256, 2) outproj_gemm_kernel(
    const float* __restrict__ bo, float* __restrict__ out_o)
{
    extern __shared__ float sm[];
    int row0 = blockIdx.x * 128;
    int n0 = blockIdx.y * 128;

    float c[2][8][4];
    mma_gemm(g_attn + (size_t)row0 * D_IN, D_IN, g_woT + (size_t)n0 * D_IN, D_IN,
             D_IN / 32, sm, c);

    #pragma unroll
    for (int mt = 0; mt < 2; mt++)
        #pragma unroll
        for (int half = 0; half < 2; half++) {
            int r = row0 + EPI_ROW(mt, half);
            #pragma unroll
            for (int nt = 0; nt < 8; nt++) {
                int cl = EPI_COL(nt);
                float2 v;
                v.x = c[mt][nt][half*2+0] + bo[n0 + cl];
                v.y = c[mt][nt][half*2+1] + bo[n0 + cl + 1];
                *(float2*)&out_o[(size_t)r * D_IN + n0 + cl] = v;
            }
        }
}

// ---------------------------------------------------------------- fused flash attention
// CTA: one (b,h) x 128 q-rows. smem: Q[128][132] + KP[128][132] + V[128][132] + red[512].
// Q, K, V pre-converted tf32; P converted at smem store.
#define SROWF 132
#define FLASH_SMEM_FLOATS (3 * 128 * SROWF + 512)
#define FLASH_SMEM_BYTES (FLASH_SMEM_FLOATS * 4)     // 204800

__global__ void __launch_bounds__(256, 1) flash_attn_kernel()
{
    extern __shared__ float sm[];
    float* Qs = sm;
    float* KP = sm + 128 * SROWF;
    float* Vs = sm + 2 * 128 * SROWF;
    float* redmax = sm + 3 * 128 * SROWF;    // [2][128]
    float* redsum = redmax + 256;            // [2][128]

    const int tid = threadIdx.x;
    const int lane = tid & 31;
    const int wid = tid >> 5;
    const int wm = wid >> 1;       // 0..3
    const int wn = wid & 1;        // 0..1

    const int bh = blockIdx.y;
    const int b = bh >> 4, h = bh & 15, g = h >> 3;
    const int bg = b * 2 + g;
    const int s0 = blockIdx.x * 128;

    const uint32_t sbase = smem_u32(sm);
    const uint32_t qb = sbase;
    const uint32_t kpb = sbase + 128 * SROWF * 4;
    const uint32_t vb = sbase + 2 * 128 * SROWF * 4;

    // staging: 2 threads per row, 64 floats (16 x 16B) per thread
    const int srow = tid >> 1;           // 0..127
    const int scb  = (tid & 1) * 64;     // float col base: 0 or 64

    // stage Q (group 0)
    {
        const float* qsrc = g_q + (((size_t)b * HEADS + h) * SEQ + s0) * HD;
        #pragma unroll
        for (int q = 0; q < 16; q++)
            CP_ASYNC16(qb + (srow * SROWF + scb + q * 4) * 4,
                       qsrc + (size_t)srow * HD + scb + q * 4);
        CP_COMMIT();
    }

    const float* kptr = g_kc + ((size_t)b * T_TOT * GROUPS + g) * HD;  // row t, stride 256
    const float* vptr = g_vT + (size_t)bg * HD * T_TOT;                // row hd, stride 768

    float m_[2][2], l_[2][2], co[2][8][4];
    #pragma unroll
    for (int mt = 0; mt < 2; mt++)
        #pragma unroll
        for (int half = 0; half < 2; half++) { m_[mt][half] = -1e30f; l_[mt][half] = 0.f; }
    #pragma unroll
    for (int mt = 0; mt < 2; mt++)
        #pragma unroll
        for (int nt = 0; nt < 8; nt++)
            #pragma unroll
            for (int q = 0; q < 4; q++) co[mt][nt][q] = 0.f;

    const uint32_t* ap = (const uint32_t*)Qs + (wm * 32 + (lane >> 2)) * SROWF + (lane & 3);
    const uint32_t* bpK = (const uint32_t*)KP + (wn * 64 + (lane >> 2)) * SROWF + (lane & 3);
    const uint32_t* bpV = (const uint32_t*)Vs + (wn * 64 + (lane >> 2)) * SROWF + (lane & 3);

    int myrow[2][2];
    #pragma unroll
    for (int mt = 0; mt < 2; mt++)
        #pragma unroll
        for (int half = 0; half < 2; half++)
            myrow[mt][half] = wm * 32 + mt * 16 + (lane >> 2) + half * 8;

    for (int tc = 0; tc < T_TOT / 128; tc++) {
        const int t0 = tc * 128;
        // stage K (one group), then V (one group)
        #pragma unroll
        for (int q = 0; q < 16; q++)
            CP_ASYNC16(kpb + (srow * SROWF + scb + q * 4) * 4,
                       kptr + (size_t)(t0 + srow) * (GROUPS * HD) + scb + q * 4);
        CP_COMMIT();
        #pragma unroll
        for (int q = 0; q < 16; q++)
            CP_ASYNC16(vb + (srow * SROWF + scb + q * 4) * 4,
                       vptr + (size_t)srow * T_TOT + t0 + scb + q * 4);
        CP_COMMIT();
        CP_WAIT1();          // Q + K ready; V may lag
        __syncthreads();

        // ---- S = Q @ K^T  (128x128, 16 k-steps of 8)
        float cs[2][8][4];
        #pragma unroll
        for (int mt = 0; mt < 2; mt++)
            #pragma unroll
            for (int nt = 0; nt < 8; nt++)
                #pragma unroll
                for (int q = 0; q < 4; q++) cs[mt][nt][q] = 0.f;

        #pragma unroll
        for (int ks = 0; ks < 16; ks++) {
            uint32_t af[2][4];
            #pragma unroll
            for (int mt = 0; mt < 2; mt++) {
                const uint32_t* p = ap + mt * 16 * SROWF + ks * 8;
                af[mt][0] = p[0];
                af[mt][1] = p[8 * SROWF];
                af[mt][2] = p[4];
                af[mt][3] = p[8 * SROWF + 4];
            }
            #pragma unroll
            for (int nt = 0; nt < 8; nt++) {
                const uint32_t* p = bpK + nt * 8 * SROWF + ks * 8;
                uint32_t b0 = p[0], b1 = p[4];
                #pragma unroll
                for (int mt = 0; mt < 2; mt++)
                    mma_tf32(cs[mt][nt], af[mt][0], af[mt][1], af[mt][2], af[mt][3], b0, b1);
            }
        }

        // ---- online softmax: row max (quad shuffle + cross-warp smem)
        #pragma unroll
        for (int mt = 0; mt < 2; mt++)
            #pragma unroll
            for (int half = 0; half < 2; half++) {
                float mx = -1e30f;
                #pragma unroll
                for (int nt = 0; nt < 8; nt++)
                    mx = fmaxf(mx, fmaxf(cs[mt][nt][half*2], cs[mt][nt][half*2+1]));
                mx = fmaxf(mx, __shfl_xor_sync(0xffffffffu, mx, 1));
                mx = fmaxf(mx, __shfl_xor_sync(0xffffffffu, mx, 2));
                if ((lane & 3) == 0) redmax[wn * 128 + myrow[mt][half]] = mx;
            }
        __syncthreads();   // also: all warps done reading K from KP

        float sc[2][2];
        #pragma unroll
        for (int mt = 0; mt < 2; mt++)
            #pragma unroll
            for (int half = 0; half < 2; half++) {
                int r = myrow[mt][half];
                float mnew = fmaxf(m_[mt][half], fmaxf(redmax[r], redmax[128 + r]));
                sc[mt][half] = __expf(m_[mt][half] - mnew);
                m_[mt][half] = mnew;
            }

        // exp, partial sums, write P (tf32 bits) into KP
        #pragma unroll
        for (int mt = 0; mt < 2; mt++)
            #pragma unroll
            for (int half = 0; half < 2; half++) {
                int r = myrow[mt][half];
                float mnew = m_[mt][half];
                float sum = 0.f;
                float* prow = KP + r * SROWF + wn * 64 + (lane & 3) * 2;
                #pragma unroll
                for (int nt = 0; nt < 8; nt++) {
                    float p0 = __expf(cs[mt][nt][half*2+0] - mnew);
                    float p1 = __expf(cs[mt][nt][half*2+1] - mnew);
                    sum += p0 + p1;
                    *(float2*)&prow[nt * 8] = make_float2(f2tf32f(p0), f2tf32f(p1));
                }
                sum += __shfl_xor_sync(0xffffffffu, sum, 1);
                sum += __shfl_xor_sync(0xffffffffu, sum, 2);
                if ((lane & 3) == 0) redsum[wn * 128 + r] = sum;
            }
        CP_WAIT0();        // this thread's V copies done
        __syncthreads();   // P + redsum + everyone's V visible

        #pragma unroll
        for (int mt = 0; mt < 2; mt++)
            #pragma unroll
            for (int half = 0; half < 2; half++) {
                int r = myrow[mt][half];
                l_[mt][half] = l_[mt][half] * sc[mt][half] + redsum[r] + redsum[128 + r];
                #pragma unroll
                for (int nt = 0; nt < 8; nt++) {
                    co[mt][nt][half*2+0] *= sc[mt][half];
                    co[mt][nt][half*2+1] *= sc[mt][half];
                }
            }

        // ---- O += P @ V^T   (A = P in KP, B = Vs[hd][t])
        const uint32_t* ap2 = (const uint32_t*)KP + (wm * 32 + (lane >> 2)) * SROWF + (lane & 3);
        #pragma unroll
        for (int ks = 0; ks < 16; ks++) {
            uint32_t af[2][4];
            #pragma unroll
            for (int mt = 0; mt < 2; mt++) {
                const uint32_t* p = ap2 + mt * 16 * SROWF + ks * 8;
                af[mt][0] = p[0];
                af[mt][1] = p[8 * SROWF];
                af[mt][2] = p[4];
                af[mt][3] = p[8 * SROWF + 4];
            }
            #pragma unroll
            for (int nt = 0; nt < 8; nt++) {
                const uint32_t* p = bpV + nt * 8 * SROWF + ks * 8;
                uint32_t b0 = p[0], b1 = p[4];
                #pragma unroll
                for (int mt = 0; mt < 2; mt++)
                    mma_tf32(co[mt][nt], af[mt][0], af[mt][1], af[mt][2], af[mt][3], b0, b1);
            }
        }
        __syncthreads();   // PV done before next chunk overwrites KP/Vs
    }

    // ---- epilogue: normalize, write g_attn (b,s,h*hd) as tf32 bits
    #pragma unroll
    for (int mt = 0; mt < 2; mt++)
        #pragma unroll
        for (int half = 0; half < 2; half++) {
            int r = myrow[mt][half];
            float inv = 1.f / l_[mt][half];
            float* dst = g_attn + ((size_t)b * SEQ + s0 + r) * D_IN + h * HD
                         + wn * 64 + (lane & 3) * 2;
            #pragma unroll
            for (int nt = 0; nt < 8; nt++) {
                float2 v = make_float2(f2tf32f(co[mt][nt][half*2+0] * inv),
                                       f2tf32f(co[mt][nt][half*2+1] * inv));
                *(float2*)&dst[nt * 8] = v;
            }
        }
}

// ---------------------------------------------------------------- prep kernels

// x -> g_xc (tf32 bits), vectorized
__global__ void cvt_x_kernel(const float* __restrict__ x)
{
    int i = blockIdx.x * blockDim.x + threadIdx.x;   // over float4s
    float4 v = ((const float4*)x)[i];
    float4 u = make_float4(f2tf32f(v.x), f2tf32f(v.y), f2tf32f(v.z), f2tf32f(v.w));
    ((float4*)g_xc)[i] = u;
}

// src [K][N] row-major -> dst [N][K] row-major, converted to tf32 bits
__global__ void transpose_kernel(const float* __restrict__ src, float* __restrict__ dst,
                                 int K, int N)
{
    __shared__ float t[32][33];
    int n0 = blockIdx.x * 32, k0 = blockIdx.y * 32;
    int tx = threadIdx.x, ty = threadIdx.y;   // 32 x 8
    #pragma unroll
    for (int j = 0; j < 32; j += 8)
        t[ty + j][tx] = src[(size_t)(k0 + ty + j) * N + n0 + tx];
    __syncthreads();
    #pragma unroll
    for (int j = 0; j < 32; j += 8)
        dst[(size_t)(n0 + ty + j) * K + k0 + tx] = f2tf32f(t[tx][ty + j]);
}

__global__ void bias_combine_kernel(const float* __restrict__ bq,
                                    const float* __restrict__ bk,
                                    const float* __restrict__ bv)
{
    int i = blockIdx.x * blockDim.x + threadIdx.x;
    if (i >= QKV_N) return;
    float v;
    if (i < 2048) v = bq[i];
    else if (i < 2304) v = bk[i - 2048];
    else v = bv[i - 2304];
    g_bias[i] = v;
}

__global__ void rope_q_kernel()
{
    int idx = blockIdx.x * blockDim.x + threadIdx.x;
    int j = idx & 63;
    int h = (idx >> 6) & 15;
    int m = idx >> 10;
    const float* src = g_qkv + (size_t)m * QKV_N + h * HD;
    float x1 = src[j], x2 = src[j + 64];
    int s = m & 511, b = m >> 9;
    float pos = (float)(CACHE + s);
    float freq = pos * expf(-(float)j * (9.210340371976184f / 64.f));
    float sn, cs; sincosf(freq, &sn, &cs);
    const float SCALE = 0.08838834764831845f;
    float* dst = g_q + (((size_t)b * HEADS + h) * SEQ + s) * HD;
    dst[j]      = f2tf32f((x1 * cs - x2 * sn) * SCALE);
    dst[j + 64] = f2tf32f((x2 * cs + x1 * sn) * SCALE);
}

__global__ void rope_kv_kernel(float* __restrict__ out_k, float* __restrict__ out_v)
{
    int idx = blockIdx.x * blockDim.x + threadIdx.x;
    int j = idx & 63;
    int g = (idx >> 6) & 1;
    int m = idx >> 7;
    const float* ksrc = g_qkv + (size_t)m * QKV_N + 2048 + g * HD;
    const float* vsrc = g_qkv + (size_t)m * QKV_N + 2304 + g * HD;
    float x1 = ksrc[j], x2 = ksrc[j + 64];
    int s = m & 511, b = m >> 9;
    float pos = (float)(CACHE + s);
    float freq = pos * expf(-(float)j * (9.210340371976184f / 64.f));
    float sn, cs; sincosf(freq, &sn, &cs);
    float k1 = x1 * cs - x2 * sn;
    float k2 = x2 * cs + x1 * sn;
    size_t base = (((size_t)b * T_TOT + CACHE + s) * GROUPS + g) * HD;
    out_k[base + j]      = k1;
    out_k[base + j + 64] = k2;
    g_kc[base + j]       = f2tf32f(k1);
    g_kc[base + j + 64]  = f2tf32f(k2);
    out_v[base + j]      = vsrc[j];
    out_v[base + j + 64] = vsrc[j + 64];
}

__global__ void copy_prev_kernel(const float* __restrict__ prev_k,
                                 const float* __restrict__ prev_v,
                                 float* __restrict__ out_k,
                                 float* __restrict__ out_v)
{
    int idx = blockIdx.x * blockDim.x + threadIdx.x;
    if (idx >= BATCH * CACHE * GROUPS * HD) return;
    int b = idx >> 16;
    int r = idx & 65535;
    float kv = prev_k[idx];
    out_k[(size_t)b * (T_TOT * GROUPS * HD) + r] = kv;
    g_kc[(size_t)b * (T_TOT * GROUPS * HD) + r]  = f2tf32f(kv);
    out_v[(size_t)b * (T_TOT * GROUPS * HD) + r] = prev_v[idx];
}

__global__ void vt_prev_kernel(const float* __restrict__ prev_v)
{
    int idx = blockIdx.x * blockDim.x + threadIdx.x;   // 16*128*256
    int t = idx & 255;
    int hd = (idx >> 8) & 127;
    int bg = idx >> 15;
    int b = bg >> 1, g = bg & 1;
    g_vT[(size_t)bg * HD * T_TOT + (size_t)hd * T_TOT + t] =
        f2tf32f(prev_v[(((size_t)b * CACHE + t) * GROUPS + g) * HD + hd]);
}

__global__ void vt_new_kernel()
{
    int idx = blockIdx.x * blockDim.x + threadIdx.x;   // 16*128*512
    int s = idx & 511;
    int hd = (idx >> 9) & 127;
    int bg = idx >> 16;
    int b = bg >> 1, g = bg & 1;
    g_vT[(size_t)bg * HD * T_TOT + (size_t)hd * T_TOT + CACHE + s] =
        f2tf32f(g_qkv[((size_t)b * SEQ + s) * QKV_N + 2304 + g * HD + hd]);
}

// ---------------------------------------------------------------- launcher
extern "C" void kernel_launch(void* const* d_in, const int* in_sizes, int n_in,
                              void* d_out, int out_size)
{
    const float* x      = (const float*)d_in[0];
    const float* prev_k = (const float*)d_in[1];
    const float* prev_v = (const float*)d_in[2];
    const float* Wq     = (const float*)d_in[3];
    const float* bq     = (const float*)d_in[4];
    const float* Wk     = (const float*)d_in[5];
    const float* bk     = (const float*)d_in[6];
    const float* Wv     = (const float*)d_in[7];
    const float* bv     = (const float*)d_in[8];
    const float* Wo     = (const float*)d_in[9];
    const float* bo     = (const float*)d_in[10];

    float* out_o = (float*)d_out;
    float* out_k = out_o + OUT_O_SIZE;
    float* out_v = out_k + OUT_K_SIZE;

    static bool attr_set = false;
    if (!attr_set) {
        cudaFuncSetAttribute(qkv_gemm_kernel,     cudaFuncAttributeMaxDynamicSharedMemorySize, GEMM_SMEM_BYTES);
        cudaFuncSetAttribute(outproj_gemm_kernel, cudaFuncAttributeMaxDynamicSharedMemorySize, GEMM_SMEM_BYTES);
        cudaFuncSetAttribute(flash_attn_kernel,   cudaFuncAttributeMaxDynamicSharedMemorySize, FLASH_SMEM_BYTES);
        attr_set = true;
    }

    // 0. Operand preparation: convert x; transpose+convert weights; bias combine
    cvt_x_kernel<<<(M_ROWS * D_IN / 4) / 256, 256>>>(x);
    {
        float* wT = nullptr; cudaGetSymbolAddress((void**)&wT, g_wT);
        float* woT = nullptr; cudaGetSymbolAddress((void**)&woT, g_woT);
        dim3 blk(32, 8);
        transpose_kernel<<<dim3(64, 64), blk>>>(Wq, wT, D_IN, D_IN);
        transpose_kernel<<<dim3(8, 64), blk>>>(Wk, wT + 2048 * D_IN, D_IN, 256);
        transpose_kernel<<<dim3(8, 64), blk>>>(Wv, wT + 2304 * D_IN, D_IN, 256);
        transpose_kernel<<<dim3(64, 64), blk>>>(Wo, woT, D_IN, D_IN);
        bias_combine_kernel<<<(QKV_N + 255) / 256, 256>>>(bq, bk, bv);
    }

    // 1. kv-cache history (+ converted K cache + transposed V history)
    copy_prev_kernel<<<2048, 256>>>(prev_k, prev_v, out_k, out_v);
    vt_prev_kernel<<<(16 * 128 * 256) / 256, 256>>>(prev_v);

    // 2. QKV projection
    qkv_gemm_kernel<<<dim3(M_ROWS / 128, QKV_N / 128), 256, GEMM_SMEM_BYTES>>>();

    // 3. RoPE q / RoPE k + v copy / transposed V
    rope_q_kernel<<<M_ROWS * HEADS * 64 / 256, 256>>>();
    rope_kv_kernel<<<M_ROWS * GROUPS * 64 / 256, 256>>>(out_k, out_v);
    vt_new_kernel<<<(16 * 128 * 512) / 256, 256>>>();

    // 4. Fused flash attention (scores + softmax + PV)
    flash_attn_kernel<<<dim3(SEQ / 128, BATCH * HEADS), 256, FLASH_SMEM_BYTES>>>();

    // 5. Output projection
    outproj_gemm_kernel<<<dim3(M_ROWS / 128, D_IN / 128), 256, GEMM_SMEM_BYTES>>>(bo, out_o);
}

// round 9
// speedup vs baseline: 1.7428x; 1.6187x over previous
#include <cuda_runtime.h>
#include <cuda_fp16.h>
#include <cstdint>
#include <math.h>

// ---------------------------------------------------------------- constants
#define D_IN    2048
#define HEADS   16
#define GROUPS  2
#define HD      128
#define BATCH   8
#define SEQ     512
#define CACHE   256
#define T_TOT   768
#define M_ROWS  (BATCH*SEQ)                 // 4096
#define QKV_N   2560
#define OUT_O_SIZE (M_ROWS*D_IN)
#define OUT_K_SIZE (BATCH*T_TOT*GROUPS*HD)

// ---------------------------------------------------------------- scratch
// fp16 GEMM operands (pre-converted by producers)
__device__ __half g_xc[M_ROWS * D_IN];
__device__ float  g_qkv[M_ROWS * QKV_N];            // projection out (fp32)
__device__ __half g_q[M_ROWS * D_IN];               // roped+scaled q (b,h,s,hd)
__device__ __half g_attn[M_ROWS * D_IN];            // attention out (b,s,h*hd)
__device__ __half g_wT[QKV_N * D_IN];               // [n_qkv][2048]
__device__ __half g_woT[D_IN * D_IN];               // [n][2048]
__device__ __half g_kc[BATCH * T_TOT * GROUPS * HD];// roped k cache
__device__ __half g_vT[16 * HD * T_TOT];            // per bg: [hd][768]
__device__ float  g_bias[QKV_N];

// ---------------------------------------------------------------- helpers
__device__ __forceinline__ uint32_t smem_u32(const void* p) {
    uint32_t a;
    asm("{ .reg .u64 t; cvta.to.shared.u64 t, %1; cvt.u32.u64 %0, t; }" : "=r"(a) : "l"(p));
    return a;
}
__device__ __forceinline__ void mma_f16(float c[4],
                                        uint32_t a0, uint32_t a1, uint32_t a2, uint32_t a3,
                                        uint32_t b0, uint32_t b1) {
    asm volatile(
        "mma.sync.aligned.m16n8k16.row.col.f32.f16.f16.f32 "
        "{%0,%1,%2,%3}, {%4,%5,%6,%7}, {%8,%9}, {%0,%1,%2,%3};"
        : "+f"(c[0]), "+f"(c[1]), "+f"(c[2]), "+f"(c[3])
        : "r"(a0), "r"(a1), "r"(a2), "r"(a3), "r"(b0), "r"(b1));
}

#define CP_ASYNC16(dst, src) \
    asm volatile("cp.async.cg.shared.global [%0], [%1], 16;" :: "r"(dst), "l"(src) : "memory")
#define CP_COMMIT() asm volatile("cp.async.commit_group;" ::: "memory")
#define CP_WAIT2()  asm volatile("cp.async.wait_group 2;" ::: "memory")
#define CP_WAIT1()  asm volatile("cp.async.wait_group 1;" ::: "memory")
#define CP_WAIT0()  asm volatile("cp.async.wait_group 0;" ::: "memory")

// ---------------------------------------------------------------- GEMM core (fp16)
// CTA tile 128x128, K chunk 32 (2 ksteps of 16), 256 threads = 8 warps (4m x 2n),
// warp 32x64. 4-stage cp.async. Rows: 32 halves + pad -> 20 words (80B), conflict-free.
#define SROWH 20
#define STAGE_WORDS (2 * 128 * SROWH)            // 5120 words = 20 KB
#define NSTAGE 4
#define GEMM_SMEM_BYTES (NSTAGE * STAGE_WORDS * 4)   // 81920

__device__ __forceinline__ void mma_gemm(
    const __half* __restrict__ A, int lda,
    const __half* __restrict__ B, int ldb,
    int n_chunks, float* sm, float c[2][8][4])
{
    const int tid  = threadIdx.x;
    const int lane = tid & 31;
    const int wid  = tid >> 5;
    const int wm   = wid >> 1;
    const int wn   = wid & 1;
    const uint32_t sbase = smem_u32(sm);

    const int srow0 = tid >> 2;       // 0..63 (advance by 64)
    const int scc   = tid & 3;        // 16B chunk within row

    #pragma unroll
    for (int mt = 0; mt < 2; mt++)
        #pragma unroll
        for (int nt = 0; nt < 8; nt++)
            #pragma unroll
            for (int q = 0; q < 4; q++) c[mt][nt][q] = 0.f;

    auto issue = [&](int chunk, int stage) {
        if (chunk < n_chunks) {
            uint32_t sA = sbase + stage * (STAGE_WORDS * 4);
            uint32_t sB = sA + 128 * SROWH * 4;
            #pragma unroll
            for (int it = 0; it < 2; it++) {
                int row = srow0 + it * 64;
                const __half* ap = A + (size_t)row * lda + chunk * 32 + scc * 8;
                CP_ASYNC16(sA + (row * SROWH + scc * 4) * 4, ap);
                const __half* bp = B + (size_t)row * ldb + chunk * 32 + scc * 8;
                CP_ASYNC16(sB + (row * SROWH + scc * 4) * 4, bp);
            }
        }
        CP_COMMIT();
    };

    auto compute = [&](int s) {
        const uint32_t* As = (const uint32_t*)sm + s * STAGE_WORDS;
        const uint32_t* Bs = As + 128 * SROWH;
        const uint32_t* ap = As + (wm * 32 + (lane >> 2)) * SROWH + (lane & 3);
        const uint32_t* bp = Bs + (wn * 64 + (lane >> 2)) * SROWH + (lane & 3);
        #pragma unroll
        for (int ks = 0; ks < 2; ks++) {
            uint32_t af[2][4];
            #pragma unroll
            for (int mt = 0; mt < 2; mt++) {
                const uint32_t* p = ap + mt * 16 * SROWH + ks * 8;
                af[mt][0] = p[0];
                af[mt][1] = p[8 * SROWH];
                af[mt][2] = p[4];
                af[mt][3] = p[8 * SROWH + 4];
            }
            #pragma unroll
            for (int nt = 0; nt < 8; nt++) {
                const uint32_t* p = bp + nt * 8 * SROWH + ks * 8;
                uint32_t b0 = p[0], b1 = p[4];
                #pragma unroll
                for (int mt = 0; mt < 2; mt++)
                    mma_f16(c[mt][nt], af[mt][0], af[mt][1], af[mt][2], af[mt][3], b0, b1);
            }
        }
    };

    issue(0, 0);
    issue(1, 1);
    issue(2, 2);
    for (int i = 0; i < n_chunks; i++) {
        issue(i + 3, (i + 3) & 3);
        CP_WAIT2();
        __syncthreads();
        compute(i & 3);
        __syncthreads();
    }
}

#define EPI_ROW(mt, half_)  (( (threadIdx.x >> 6) & 3 ) * 32 + (mt) * 16 + ((threadIdx.x & 31) >> 2) + (half_) * 8)
#define EPI_COL(nt)         (( (threadIdx.x >> 5) & 1 ) * 64 + (nt) * 8 + ((threadIdx.x & 31) & 3) * 2)

// ---------------------------------------------------------------- projection kernels

__global__ void __launch_bounds__(256, 2) qkv_gemm_kernel()
{
    extern __shared__ float sm[];
    int row0 = blockIdx.x * 128;
    int n0 = blockIdx.y * 128;

    float c[2][8][4];
    mma_gemm(g_xc + (size_t)row0 * D_IN, D_IN, g_wT + (size_t)n0 * D_IN, D_IN,
             D_IN / 32, sm, c);

    #pragma unroll
    for (int mt = 0; mt < 2; mt++)
        #pragma unroll
        for (int hf = 0; hf < 2; hf++) {
            int r = row0 + EPI_ROW(mt, hf);
            #pragma unroll
            for (int nt = 0; nt < 8; nt++) {
                int cl = EPI_COL(nt);
                float2 v;
                v.x = c[mt][nt][hf*2+0] + g_bias[n0 + cl];
                v.y = c[mt][nt][hf*2+1] + g_bias[n0 + cl + 1];
                *(float2*)&g_qkv[(size_t)r * QKV_N + n0 + cl] = v;
            }
        }
}

__global__ void __launch_bounds__(256, 2) outproj_gemm_kernel(
    const float* __restrict__ bo, float* __restrict__ out_o)
{
    extern __shared__ float sm[];
    int row0 = blockIdx.x * 128;
    int n0 = blockIdx.y * 128;

    float c[2][8][4];
    mma_gemm(g_attn + (size_t)row0 * D_IN, D_IN, g_woT + (size_t)n0 * D_IN, D_IN,
             D_IN / 32, sm, c);

    #pragma unroll
    for (int mt = 0; mt < 2; mt++)
        #pragma unroll
        for (int hf = 0; hf < 2; hf++) {
            int r = row0 + EPI_ROW(mt, hf);
            #pragma unroll
            for (int nt = 0; nt < 8; nt++) {
                int cl = EPI_COL(nt);
                float2 v;
                v.x = c[mt][nt][hf*2+0] + bo[n0 + cl];
                v.y = c[mt][nt][hf*2+1] + bo[n0 + cl + 1];
                *(float2*)&out_o[(size_t)r * D_IN + n0 + cl] = v;
            }
        }
}

// ---------------------------------------------------------------- fused flash attention (fp16)
// CTA: one (b,h) x 128 q-rows. Tiles 128x128 fp16, rows 128 halves + 8 pad = 68 words.
#define SROWFW 68
#define FLASH_TILE_W (128 * SROWFW)                   // 8704 words
#define FLASH_SMEM_BYTES ((3 * FLASH_TILE_W + 512) * 4)  // 106496

__global__ void __launch_bounds__(256, 1) flash_attn_kernel()
{
    extern __shared__ float sm[];
    uint32_t* Qw = (uint32_t*)sm;
    uint32_t* KPw = Qw + FLASH_TILE_W;
    uint32_t* Vw = Qw + 2 * FLASH_TILE_W;
    float* redmax = sm + 3 * FLASH_TILE_W;   // [2][128]
    float* redsum = redmax + 256;            // [2][128]

    const int tid = threadIdx.x;
    const int lane = tid & 31;
    const int wid = tid >> 5;
    const int wm = wid >> 1;       // 0..3
    const int wn = wid & 1;        // 0..1

    const int bh = blockIdx.y;
    const int b = bh >> 4, h = bh & 15, g = h >> 3;
    const int bg = b * 2 + g;
    const int s0 = blockIdx.x * 128;

    const uint32_t sbase = smem_u32(sm);
    const uint32_t qb = sbase;
    const uint32_t kpb = sbase + FLASH_TILE_W * 4;
    const uint32_t vb = sbase + 2 * FLASH_TILE_W * 4;

    // staging: 2 threads per row, 8 x 16B chunks per thread
    const int srow = tid >> 1;           // 0..127
    const int scb  = (tid & 1) * 8;      // chunk base (16B units)

    // stage Q (group 0)
    {
        const __half* qsrc = g_q + (((size_t)b * HEADS + h) * SEQ + s0) * HD;
        #pragma unroll
        for (int q = 0; q < 8; q++)
            CP_ASYNC16(qb + (srow * SROWFW + (scb + q) * 4) * 4,
                       qsrc + (size_t)srow * HD + (scb + q) * 8);
        CP_COMMIT();
    }

    const __half* kptr = g_kc + ((size_t)b * T_TOT * GROUPS + g) * HD;  // row t, stride 256
    const __half* vptr = g_vT + (size_t)bg * HD * T_TOT;                // row hd, stride 768

    float m_[2][2], l_[2][2], co[2][8][4];
    #pragma unroll
    for (int mt = 0; mt < 2; mt++)
        #pragma unroll
        for (int hf = 0; hf < 2; hf++) { m_[mt][hf] = -1e30f; l_[mt][hf] = 0.f; }
    #pragma unroll
    for (int mt = 0; mt < 2; mt++)
        #pragma unroll
        for (int nt = 0; nt < 8; nt++)
            #pragma unroll
            for (int q = 0; q < 4; q++) co[mt][nt][q] = 0.f;

    const uint32_t* ap = Qw + (wm * 32 + (lane >> 2)) * SROWFW + (lane & 3);
    const uint32_t* bpK = KPw + (wn * 64 + (lane >> 2)) * SROWFW + (lane & 3);
    const uint32_t* bpV = Vw + (wn * 64 + (lane >> 2)) * SROWFW + (lane & 3);

    int myrow[2][2];
    #pragma unroll
    for (int mt = 0; mt < 2; mt++)
        #pragma unroll
        for (int hf = 0; hf < 2; hf++)
            myrow[mt][hf] = wm * 32 + mt * 16 + (lane >> 2) + hf * 8;

    for (int tc = 0; tc < T_TOT / 128; tc++) {
        const int t0 = tc * 128;
        // stage K (one group), then V (one group)
        #pragma unroll
        for (int q = 0; q < 8; q++)
            CP_ASYNC16(kpb + (srow * SROWFW + (scb + q) * 4) * 4,
                       kptr + (size_t)(t0 + srow) * (GROUPS * HD) + (scb + q) * 8);
        CP_COMMIT();
        #pragma unroll
        for (int q = 0; q < 8; q++)
            CP_ASYNC16(vb + (srow * SROWFW + (scb + q) * 4) * 4,
                       vptr + (size_t)srow * T_TOT + t0 + (scb + q) * 8);
        CP_COMMIT();
        CP_WAIT1();          // Q + K ready; V may lag
        __syncthreads();

        // ---- S = Q @ K^T  (128x128, 8 ksteps of 16)
        float cs[2][8][4];
        #pragma unroll
        for (int mt = 0; mt < 2; mt++)
            #pragma unroll
            for (int nt = 0; nt < 8; nt++)
                #pragma unroll
                for (int q = 0; q < 4; q++) cs[mt][nt][q] = 0.f;

        #pragma unroll
        for (int ks = 0; ks < 8; ks++) {
            uint32_t af[2][4];
            #pragma unroll
            for (int mt = 0; mt < 2; mt++) {
                const uint32_t* p = ap + mt * 16 * SROWFW + ks * 8;
                af[mt][0] = p[0];
                af[mt][1] = p[8 * SROWFW];
                af[mt][2] = p[4];
                af[mt][3] = p[8 * SROWFW + 4];
            }
            #pragma unroll
            for (int nt = 0; nt < 8; nt++) {
                const uint32_t* p = bpK + nt * 8 * SROWFW + ks * 8;
                uint32_t b0 = p[0], b1 = p[4];
                #pragma unroll
                for (int mt = 0; mt < 2; mt++)
                    mma_f16(cs[mt][nt], af[mt][0], af[mt][1], af[mt][2], af[mt][3], b0, b1);
            }
        }

        // ---- online softmax: row max (quad shuffle + cross-warp smem)
        #pragma unroll
        for (int mt = 0; mt < 2; mt++)
            #pragma unroll
            for (int hf = 0; hf < 2; hf++) {
                float mx = -1e30f;
                #pragma unroll
                for (int nt = 0; nt < 8; nt++)
                    mx = fmaxf(mx, fmaxf(cs[mt][nt][hf*2], cs[mt][nt][hf*2+1]));
                mx = fmaxf(mx, __shfl_xor_sync(0xffffffffu, mx, 1));
                mx = fmaxf(mx, __shfl_xor_sync(0xffffffffu, mx, 2));
                if ((lane & 3) == 0) redmax[wn * 128 + myrow[mt][hf]] = mx;
            }
        __syncthreads();   // all warps done reading K from KP

        float sc[2][2];
        #pragma unroll
        for (int mt = 0; mt < 2; mt++)
            #pragma unroll
            for (int hf = 0; hf < 2; hf++) {
                int r = myrow[mt][hf];
                float mnew = fmaxf(m_[mt][hf], fmaxf(redmax[r], redmax[128 + r]));
                sc[mt][hf] = __expf(m_[mt][hf] - mnew);
                m_[mt][hf] = mnew;
            }

        // exp, partial sums, write P (fp16) into KP
        #pragma unroll
        for (int mt = 0; mt < 2; mt++)
            #pragma unroll
            for (int hf = 0; hf < 2; hf++) {
                int r = myrow[mt][hf];
                float mnew = m_[mt][hf];
                float sum = 0.f;
                __half2* prow = (__half2*)KPw + r * SROWFW + wn * 32 + (lane & 3);
                #pragma unroll
                for (int nt = 0; nt < 8; nt++) {
                    float p0 = __expf(cs[mt][nt][hf*2+0] - mnew);
                    float p1 = __expf(cs[mt][nt][hf*2+1] - mnew);
                    sum += p0 + p1;
                    prow[nt * 4] = __floats2half2_rn(p0, p1);
                }
                sum += __shfl_xor_sync(0xffffffffu, sum, 1);
                sum += __shfl_xor_sync(0xffffffffu, sum, 2);
                if ((lane & 3) == 0) redsum[wn * 128 + r] = sum;
            }
        CP_WAIT0();        // this thread's V copies done
        __syncthreads();   // P + redsum + everyone's V visible

        #pragma unroll
        for (int mt = 0; mt < 2; mt++)
            #pragma unroll
            for (int hf = 0; hf < 2; hf++) {
                int r = myrow[mt][hf];
                l_[mt][hf] = l_[mt][hf] * sc[mt][hf] + redsum[r] + redsum[128 + r];
                #pragma unroll
                for (int nt = 0; nt < 8; nt++) {
                    co[mt][nt][hf*2+0] *= sc[mt][hf];
                    co[mt][nt][hf*2+1] *= sc[mt][hf];
                }
            }

        // ---- O += P @ V^T   (A = P in KP, B = Vs[hd][t])
        const uint32_t* ap2 = KPw + (wm * 32 + (lane >> 2)) * SROWFW + (lane & 3);
        #pragma unroll
        for (int ks = 0; ks < 8; ks++) {
            uint32_t af[2][4];
            #pragma unroll
            for (int mt = 0; mt < 2; mt++) {
                const uint32_t* p = ap2 + mt * 16 * SROWFW + ks * 8;
                af[mt][0] = p[0];
                af[mt][1] = p[8 * SROWFW];
                af[mt][2] = p[4];
                af[mt][3] = p[8 * SROWFW + 4];
            }
            #pragma unroll
            for (int nt = 0; nt < 8; nt++) {
                const uint32_t* p = bpV + nt * 8 * SROWFW + ks * 8;
                uint32_t b0 = p[0], b1 = p[4];
                #pragma unroll
                for (int mt = 0; mt < 2; mt++)
                    mma_f16(co[mt][nt], af[mt][0], af[mt][1], af[mt][2], af[mt][3], b0, b1);
            }
        }
        __syncthreads();   // PV done before next chunk overwrites KP/Vs
    }

    // ---- epilogue: normalize, write g_attn (fp16)
    #pragma unroll
    for (int mt = 0; mt < 2; mt++)
        #pragma unroll
        for (int hf = 0; hf < 2; hf++) {
            int r = myrow[mt][hf];
            float inv = 1.f / l_[mt][hf];
            __half2* dst = (__half2*)(g_attn + ((size_t)b * SEQ + s0 + r) * D_IN
                                      + h * HD + wn * 64 + (lane & 3) * 2);
            #pragma unroll
            for (int nt = 0; nt < 8; nt++)
                dst[nt * 4] = __floats2half2_rn(co[mt][nt][hf*2+0] * inv,
                                                co[mt][nt][hf*2+1] * inv);
        }
}

// ---------------------------------------------------------------- prep kernels

__global__ void cvt_x_kernel(const float* __restrict__ x)
{
    int i = blockIdx.x * blockDim.x + threadIdx.x;   // over float4s
    float4 v = ((const float4*)x)[i];
    ((__half2*)g_xc)[i * 2 + 0] = __floats2half2_rn(v.x, v.y);
    ((__half2*)g_xc)[i * 2 + 1] = __floats2half2_rn(v.z, v.w);
}

// src [K][N] fp32 -> dst [N][K] fp16
__global__ void transpose_kernel(const float* __restrict__ src, __half* __restrict__ dst,
                                 int K, int N)
{
    __shared__ float t[32][33];
    int n0 = blockIdx.x * 32, k0 = blockIdx.y * 32;
    int tx = threadIdx.x, ty = threadIdx.y;   // 32 x 8
    #pragma unroll
    for (int j = 0; j < 32; j += 8)
        t[ty + j][tx] = src[(size_t)(k0 + ty + j) * N + n0 + tx];
    __syncthreads();
    #pragma unroll
    for (int j = 0; j < 32; j += 8)
        dst[(size_t)(n0 + ty + j) * K + k0 + tx] = __float2half(t[tx][ty + j]);
}

__global__ void bias_combine_kernel(const float* __restrict__ bq,
                                    const float* __restrict__ bk,
                                    const float* __restrict__ bv)
{
    int i = blockIdx.x * blockDim.x + threadIdx.x;
    if (i >= QKV_N) return;
    float v;
    if (i < 2048) v = bq[i];
    else if (i < 2304) v = bk[i - 2048];
    else v = bv[i - 2304];
    g_bias[i] = v;
}

__global__ void rope_q_kernel()
{
    int idx = blockIdx.x * blockDim.x + threadIdx.x;
    int j = idx & 63;
    int h = (idx >> 6) & 15;
    int m = idx >> 10;
    const float* src = g_qkv + (size_t)m * QKV_N + h * HD;
    float x1 = src[j], x2 = src[j + 64];
    int s = m & 511, b = m >> 9;
    float pos = (float)(CACHE + s);
    float freq = pos * expf(-(float)j * (9.210340371976184f / 64.f));
    float sn, cs; sincosf(freq, &sn, &cs);
    const float SCALE = 0.08838834764831845f;
    __half* dst = g_q + (((size_t)b * HEADS + h) * SEQ + s) * HD;
    dst[j]      = __float2half((x1 * cs - x2 * sn) * SCALE);
    dst[j + 64] = __float2half((x2 * cs + x1 * sn) * SCALE);
}

__global__ void rope_kv_kernel(float* __restrict__ out_k, float* __restrict__ out_v)
{
    int idx = blockIdx.x * blockDim.x + threadIdx.x;
    int j = idx & 63;
    int g = (idx >> 6) & 1;
    int m = idx >> 7;
    const float* ksrc = g_qkv + (size_t)m * QKV_N + 2048 + g * HD;
    const float* vsrc = g_qkv + (size_t)m * QKV_N + 2304 + g * HD;
    float x1 = ksrc[j], x2 = ksrc[j + 64];
    int s = m & 511, b = m >> 9;
    float pos = (float)(CACHE + s);
    float freq = pos * expf(-(float)j * (9.210340371976184f / 64.f));
    float sn, cs; sincosf(freq, &sn, &cs);
    float k1 = x1 * cs - x2 * sn;
    float k2 = x2 * cs + x1 * sn;
    size_t base = (((size_t)b * T_TOT + CACHE + s) * GROUPS + g) * HD;
    out_k[base + j]      = k1;
    out_k[base + j + 64] = k2;
    g_kc[base + j]       = __float2half(k1);
    g_kc[base + j + 64]  = __float2half(k2);
    out_v[base + j]      = vsrc[j];
    out_v[base + j + 64] = vsrc[j + 64];
}

__global__ void copy_prev_kernel(const float* __restrict__ prev_k,
                                 const float* __restrict__ prev_v,
                                 float* __restrict__ out_k,
                                 float* __restrict__ out_v)
{
    int idx = blockIdx.x * blockDim.x + threadIdx.x;
    if (idx >= BATCH * CACHE * GROUPS * HD) return;
    int b = idx >> 16;
    int r = idx & 65535;
    float kv = prev_k[idx];
    out_k[(size_t)b * (T_TOT * GROUPS * HD) + r] = kv;
    g_kc[(size_t)b * (T_TOT * GROUPS * HD) + r]  = __float2half(kv);
    out_v[(size_t)b * (T_TOT * GROUPS * HD) + r] = prev_v[idx];
}

__global__ void vt_prev_kernel(const float* __restrict__ prev_v)
{
    int idx = blockIdx.x * blockDim.x + threadIdx.x;   // 16*128*256
    int t = idx & 255;
    int hd = (idx >> 8) & 127;
    int bg = idx >> 15;
    int b = bg >> 1, g = bg & 1;
    g_vT[(size_t)bg * HD * T_TOT + (size_t)hd * T_TOT + t] =
        __float2half(prev_v[(((size_t)b * CACHE + t) * GROUPS + g) * HD + hd]);
}

__global__ void vt_new_kernel()
{
    int idx = blockIdx.x * blockDim.x + threadIdx.x;   // 16*128*512
    int s = idx & 511;
    int hd = (idx >> 9) & 127;
    int bg = idx >> 16;
    int b = bg >> 1, g = bg & 1;
    g_vT[(size_t)bg * HD * T_TOT + (size_t)hd * T_TOT + CACHE + s] =
        __float2half(g_qkv[((size_t)b * SEQ + s) * QKV_N + 2304 + g * HD + hd]);
}

// ---------------------------------------------------------------- launcher
extern "C" void kernel_launch(void* const* d_in, const int* in_sizes, int n_in,
                              void* d_out, int out_size)
{
    const float* x      = (const float*)d_in[0];
    const float* prev_k = (const float*)d_in[1];
    const float* prev_v = (const float*)d_in[2];
    const float* Wq     = (const float*)d_in[3];
    const float* bq     = (const float*)d_in[4];
    const float* Wk     = (const float*)d_in[5];
    const float* bk     = (const float*)d_in[6];
    const float* Wv     = (const float*)d_in[7];
    const float* bv     = (const float*)d_in[8];
    const float* Wo     = (const float*)d_in[9];
    const float* bo     = (const float*)d_in[10];

    float* out_o = (float*)d_out;
    float* out_k = out_o + OUT_O_SIZE;
    float* out_v = out_k + OUT_K_SIZE;

    static bool attr_set = false;
    if (!attr_set) {
        cudaFuncSetAttribute(qkv_gemm_kernel,     cudaFuncAttributeMaxDynamicSharedMemorySize, GEMM_SMEM_BYTES);
        cudaFuncSetAttribute(outproj_gemm_kernel, cudaFuncAttributeMaxDynamicSharedMemorySize, GEMM_SMEM_BYTES);
        cudaFuncSetAttribute(flash_attn_kernel,   cudaFuncAttributeMaxDynamicSharedMemorySize, FLASH_SMEM_BYTES);
        attr_set = true;
    }

    // 0. Operand preparation
    cvt_x_kernel<<<(M_ROWS * D_IN / 4) / 256, 256>>>(x);
    {
        __half* wT = nullptr; cudaGetSymbolAddress((void**)&wT, g_wT);
        __half* woT = nullptr; cudaGetSymbolAddress((void**)&woT, g_woT);
        dim3 blk(32, 8);
        transpose_kernel<<<dim3(64, 64), blk>>>(Wq, wT, D_IN, D_IN);
        transpose_kernel<<<dim3(8, 64), blk>>>(Wk, wT + 2048 * D_IN, D_IN, 256);
        transpose_kernel<<<dim3(8, 64), blk>>>(Wv, wT + 2304 * D_IN, D_IN, 256);
        transpose_kernel<<<dim3(64, 64), blk>>>(Wo, woT, D_IN, D_IN);
        bias_combine_kernel<<<(QKV_N + 255) / 256, 256>>>(bq, bk, bv);
    }

    // 1. kv-cache history (+ fp16 K cache + transposed V history)
    copy_prev_kernel<<<2048, 256>>>(prev_k, prev_v, out_k, out_v);
    vt_prev_kernel<<<(16 * 128 * 256) / 256, 256>>>(prev_v);

    // 2. QKV projection
    qkv_gemm_kernel<<<dim3(M_ROWS / 128, QKV_N / 128), 256, GEMM_SMEM_BYTES>>>();

    // 3. RoPE q / RoPE k + v copy / transposed V
    rope_q_kernel<<<M_ROWS * HEADS * 64 / 256, 256>>>();
    rope_kv_kernel<<<M_ROWS * GROUPS * 64 / 256, 256>>>(out_k, out_v);
    vt_new_kernel<<<(16 * 128 * 512) / 256, 256>>>();

    // 4. Fused flash attention
    flash_attn_kernel<<<dim3(SEQ / 128, BATCH * HEADS), 256, FLASH_SMEM_BYTES>>>();

    // 5. Output projection
    outproj_gemm_kernel<<<dim3(M_ROWS / 128, D_IN / 128), 256, GEMM_SMEM_BYTES>>>(bo, out_o);
}

// round 11
// speedup vs baseline: 2.0738x; 1.1899x over previous
#include <cuda_runtime.h>
#include <cuda_fp16.h>
#include <cstdint>
#include <math.h>

// ---------------------------------------------------------------- constants
#define D_IN    2048
#define HEADS   16
#define GROUPS  2
#define HD      128
#define BATCH   8
#define SEQ     512
#define CACHE   256
#define T_TOT   768
#define M_ROWS  (BATCH*SEQ)                 // 4096
#define QKV_N   2560
#define OUT_O_SIZE (M_ROWS*D_IN)
#define OUT_K_SIZE (BATCH*T_TOT*GROUPS*HD)

// ---------------------------------------------------------------- scratch
__device__ __half g_xc[M_ROWS * D_IN];
__device__ float  g_qkv[M_ROWS * QKV_N];
__device__ __half g_q[M_ROWS * D_IN];               // roped+scaled q (b,h,s,hd)
__device__ __half g_attn[M_ROWS * D_IN];            // attention out (b,s,h*hd)
__device__ __half g_wT[QKV_N * D_IN];               // [n_qkv][2048]
__device__ __half g_woT[D_IN * D_IN];               // [n][2048]
__device__ __half g_kc[BATCH * T_TOT * GROUPS * HD];// roped k cache
__device__ __half g_vT[16 * HD * T_TOT];            // per bg: [hd][768]
__device__ float  g_bias[QKV_N];

// ---------------------------------------------------------------- helpers
__device__ __forceinline__ uint32_t smem_u32(const void* p) {
    uint32_t a;
    asm("{ .reg .u64 t; cvta.to.shared.u64 t, %1; cvt.u32.u64 %0, t; }" : "=r"(a) : "l"(p));
    return a;
}
__device__ __forceinline__ void mma_f16(float c[4],
                                        uint32_t a0, uint32_t a1, uint32_t a2, uint32_t a3,
                                        uint32_t b0, uint32_t b1) {
    asm volatile(
        "mma.sync.aligned.m16n8k16.row.col.f32.f16.f16.f32 "
        "{%0,%1,%2,%3}, {%4,%5,%6,%7}, {%8,%9}, {%0,%1,%2,%3};"
        : "+f"(c[0]), "+f"(c[1]), "+f"(c[2]), "+f"(c[3])
        : "r"(a0), "r"(a1), "r"(a2), "r"(a3), "r"(b0), "r"(b1));
}
__device__ __forceinline__ void ldsm_x4(uint32_t* r, uint32_t addr) {
    asm volatile("ldmatrix.sync.aligned.m8n8.x4.shared.b16 {%0,%1,%2,%3}, [%4];"
        : "=r"(r[0]), "=r"(r[1]), "=r"(r[2]), "=r"(r[3]) : "r"(addr));
}

#define CP_ASYNC16(dst, src) \
    asm volatile("cp.async.cg.shared.global [%0], [%1], 16;" :: "r"(dst), "l"(src) : "memory")
#define CP_COMMIT() asm volatile("cp.async.commit_group;" ::: "memory")
#define CP_WAIT2()  asm volatile("cp.async.wait_group 2;" ::: "memory")
#define CP_WAIT1()  asm volatile("cp.async.wait_group 1;" ::: "memory")
#define CP_WAIT0()  asm volatile("cp.async.wait_group 0;" ::: "memory")

// ---------------------------------------------------------------- GEMM core (fp16, ldmatrix)
// CTA tile 128x128, K chunk 32 (2 ksteps of 16), 256 threads = 8 warps (4m x 2n),
// warp 32x64. 4-stage cp.async, ONE barrier per chunk. Rows: 32 halves + pad = 20 words.
#define SROWH 20
#define STAGE_WORDS (2 * 128 * SROWH)            // 5120 words = 20 KB
#define NSTAGE 4
#define GEMM_SMEM_BYTES (NSTAGE * STAGE_WORDS * 4)   // 81920

__device__ __forceinline__ void mma_gemm(
    const __half* __restrict__ A, int lda,
    const __half* __restrict__ B, int ldb,
    int n_chunks, float* sm, float c[2][8][4])
{
    const int tid  = threadIdx.x;
    const int lane = tid & 31;
    const int wid  = tid >> 5;
    const int wm   = wid >> 1;
    const int wn   = wid & 1;
    const uint32_t sbase = smem_u32(sm);

    const int srow0 = tid >> 2;       // 0..63 (advance by 64)
    const int scc   = tid & 3;        // 16B chunk within row

    #pragma unroll
    for (int mt = 0; mt < 2; mt++)
        #pragma unroll
        for (int nt = 0; nt < 8; nt++)
            #pragma unroll
            for (int q = 0; q < 4; q++) c[mt][nt][q] = 0.f;

    auto issue = [&](int chunk, int stage) {
        if (chunk < n_chunks) {
            uint32_t sA = sbase + stage * (STAGE_WORDS * 4);
            uint32_t sB = sA + 128 * SROWH * 4;
            #pragma unroll
            for (int it = 0; it < 2; it++) {
                int row = srow0 + it * 64;
                const __half* ap = A + (size_t)row * lda + chunk * 32 + scc * 8;
                CP_ASYNC16(sA + (row * SROWH + scc * 4) * 4, ap);
                const __half* bp = B + (size_t)row * ldb + chunk * 32 + scc * 8;
                CP_ASYNC16(sB + (row * SROWH + scc * 4) * 4, bp);
            }
        }
        CP_COMMIT();
    };

    // ldmatrix lane-address offsets (bytes)
    const uint32_t aoff = ((uint32_t)(wm * 32 + (lane & 15)) * SROWH + (lane >> 4) * 4) * 4;
    const uint32_t boff = ((uint32_t)(wn * 64 + ((lane >> 4) & 1) * 8 + (lane & 7)) * SROWH
                           + ((lane >> 3) & 1) * 4) * 4;

    auto compute = [&](int s) {
        uint32_t sA = sbase + s * (STAGE_WORDS * 4);
        uint32_t sB = sA + 128 * SROWH * 4;
        uint32_t aAddr = sA + aoff;
        uint32_t bAddr = sB + boff;
        #pragma unroll
        for (int ks = 0; ks < 2; ks++) {
            uint32_t af[2][4];
            ldsm_x4(af[0], aAddr + ks * 32);
            ldsm_x4(af[1], aAddr + 16 * SROWH * 4 + ks * 32);
            #pragma unroll
            for (int j = 0; j < 4; j++) {
                uint32_t bb[4];
                ldsm_x4(bb, bAddr + j * 16 * SROWH * 4 + ks * 32);
                mma_f16(c[0][2*j],   af[0][0], af[0][1], af[0][2], af[0][3], bb[0], bb[1]);
                mma_f16(c[1][2*j],   af[1][0], af[1][1], af[1][2], af[1][3], bb[0], bb[1]);
                mma_f16(c[0][2*j+1], af[0][0], af[0][1], af[0][2], af[0][3], bb[2], bb[3]);
                mma_f16(c[1][2*j+1], af[1][0], af[1][1], af[1][2], af[1][3], bb[2], bb[3]);
            }
        }
    };

    issue(0, 0);
    issue(1, 1);
    issue(2, 2);
    for (int i = 0; i < n_chunks; i++) {
        CP_WAIT2();
        __syncthreads();           // single barrier per chunk
        compute(i & 3);
        issue(i + 3, (i + 3) & 3); // writes stage (i-1)&3, consumed before this barrier
    }
}

#define EPI_ROW(mt, half_)  (( (threadIdx.x >> 6) & 3 ) * 32 + (mt) * 16 + ((threadIdx.x & 31) >> 2) + (half_) * 8)
#define EPI_COL(nt)         (( (threadIdx.x >> 5) & 1 ) * 64 + (nt) * 8 + ((threadIdx.x & 31) & 3) * 2)

// ---------------------------------------------------------------- projection kernels

__global__ void __launch_bounds__(256, 2) qkv_gemm_kernel()
{
    extern __shared__ float sm[];
    int row0 = blockIdx.x * 128;
    int n0 = blockIdx.y * 128;

    float c[2][8][4];
    mma_gemm(g_xc + (size_t)row0 * D_IN, D_IN, g_wT + (size_t)n0 * D_IN, D_IN,
             D_IN / 32, sm, c);

    #pragma unroll
    for (int mt = 0; mt < 2; mt++)
        #pragma unroll
        for (int hf = 0; hf < 2; hf++) {
            int r = row0 + EPI_ROW(mt, hf);
            #pragma unroll
            for (int nt = 0; nt < 8; nt++) {
                int cl = EPI_COL(nt);
                float2 v;
                v.x = c[mt][nt][hf*2+0] + g_bias[n0 + cl];
                v.y = c[mt][nt][hf*2+1] + g_bias[n0 + cl + 1];
                *(float2*)&g_qkv[(size_t)r * QKV_N + n0 + cl] = v;
            }
        }
}

__global__ void __launch_bounds__(256, 2) outproj_gemm_kernel(
    const float* __restrict__ bo, float* __restrict__ out_o)
{
    extern __shared__ float sm[];
    int row0 = blockIdx.x * 128;
    int n0 = blockIdx.y * 128;

    float c[2][8][4];
    mma_gemm(g_attn + (size_t)row0 * D_IN, D_IN, g_woT + (size_t)n0 * D_IN, D_IN,
             D_IN / 32, sm, c);

    #pragma unroll
    for (int mt = 0; mt < 2; mt++)
        #pragma unroll
        for (int hf = 0; hf < 2; hf++) {
            int r = row0 + EPI_ROW(mt, hf);
            #pragma unroll
            for (int nt = 0; nt < 8; nt++) {
                int cl = EPI_COL(nt);
                float2 v;
                v.x = c[mt][nt][hf*2+0] + bo[n0 + cl];
                v.y = c[mt][nt][hf*2+1] + bo[n0 + cl + 1];
                *(float2*)&out_o[(size_t)r * D_IN + n0 + cl] = v;
            }
        }
}

// ---------------------------------------------------------------- fused flash attention (fp16, ldmatrix)
#define SROWFW 68
#define FLASH_TILE_W (128 * SROWFW)                   // 8704 words
#define FLASH_SMEM_BYTES ((3 * FLASH_TILE_W + 512) * 4)  // 106496

__global__ void __launch_bounds__(256, 1) flash_attn_kernel()
{
    extern __shared__ float sm[];
    uint32_t* KPw = (uint32_t*)sm + FLASH_TILE_W;
    float* redmax = sm + 3 * FLASH_TILE_W;   // [2][128]
    float* redsum = redmax + 256;            // [2][128]

    const int tid = threadIdx.x;
    const int lane = tid & 31;
    const int wid = tid >> 5;
    const int wm = wid >> 1;       // 0..3
    const int wn = wid & 1;        // 0..1

    const int bh = blockIdx.y;
    const int b = bh >> 4, h = bh & 15, g = h >> 3;
    const int bg = b * 2 + g;
    const int s0 = blockIdx.x * 128;

    const uint32_t sbase = smem_u32(sm);
    const uint32_t qb = sbase;
    const uint32_t kpb = sbase + FLASH_TILE_W * 4;
    const uint32_t vb = sbase + 2 * FLASH_TILE_W * 4;

    // staging: 2 threads per row, 8 x 16B chunks per thread
    const int srow = tid >> 1;
    const int scb  = (tid & 1) * 8;

    // stage Q (group 0)
    {
        const __half* qsrc = g_q + (((size_t)b * HEADS + h) * SEQ + s0) * HD;
        #pragma unroll
        for (int q = 0; q < 8; q++)
            CP_ASYNC16(qb + (srow * SROWFW + (scb + q) * 4) * 4,
                       qsrc + (size_t)srow * HD + (scb + q) * 8);
        CP_COMMIT();
    }

    const __half* kptr = g_kc + ((size_t)b * T_TOT * GROUPS + g) * HD;
    const __half* vptr = g_vT + (size_t)bg * HD * T_TOT;

    float m_[2][2], l_[2][2], co[2][8][4];
    #pragma unroll
    for (int mt = 0; mt < 2; mt++)
        #pragma unroll
        for (int hf = 0; hf < 2; hf++) { m_[mt][hf] = -1e30f; l_[mt][hf] = 0.f; }
    #pragma unroll
    for (int mt = 0; mt < 2; mt++)
        #pragma unroll
        for (int nt = 0; nt < 8; nt++)
            #pragma unroll
            for (int q = 0; q < 4; q++) co[mt][nt][q] = 0.f;

    // ldmatrix lane-address offsets (bytes)
    const uint32_t aoffF = ((uint32_t)(wm * 32 + (lane & 15)) * SROWFW + (lane >> 4) * 4) * 4;
    const uint32_t boffF = ((uint32_t)(wn * 64 + ((lane >> 4) & 1) * 8 + (lane & 7)) * SROWFW
                            + ((lane >> 3) & 1) * 4) * 4;
    const uint32_t aAddrQ = qb + aoffF;
    const uint32_t bAddrK = kpb + boffF;
    const uint32_t bAddrV = vb + boffF;
    const uint32_t aAddrP = kpb + aoffF;

    int myrow[2][2];
    #pragma unroll
    for (int mt = 0; mt < 2; mt++)
        #pragma unroll
        for (int hf = 0; hf < 2; hf++)
            myrow[mt][hf] = wm * 32 + mt * 16 + (lane >> 2) + hf * 8;

    for (int tc = 0; tc < T_TOT / 128; tc++) {
        const int t0 = tc * 128;
        #pragma unroll
        for (int q = 0; q < 8; q++)
            CP_ASYNC16(kpb + (srow * SROWFW + (scb + q) * 4) * 4,
                       kptr + (size_t)(t0 + srow) * (GROUPS * HD) + (scb + q) * 8);
        CP_COMMIT();
        #pragma unroll
        for (int q = 0; q < 8; q++)
            CP_ASYNC16(vb + (srow * SROWFW + (scb + q) * 4) * 4,
                       vptr + (size_t)srow * T_TOT + t0 + (scb + q) * 8);
        CP_COMMIT();
        CP_WAIT1();          // Q + K ready; V may lag
        __syncthreads();

        // ---- S = Q @ K^T  (128x128, 8 ksteps)
        float cs[2][8][4];
        #pragma unroll
        for (int mt = 0; mt < 2; mt++)
            #pragma unroll
            for (int nt = 0; nt < 8; nt++)
                #pragma unroll
                for (int q = 0; q < 4; q++) cs[mt][nt][q] = 0.f;

        #pragma unroll
        for (int ks = 0; ks < 8; ks++) {
            uint32_t af[2][4];
            ldsm_x4(af[0], aAddrQ + ks * 32);
            ldsm_x4(af[1], aAddrQ + 16 * SROWFW * 4 + ks * 32);
            #pragma unroll
            for (int j = 0; j < 4; j++) {
                uint32_t bb[4];
                ldsm_x4(bb, bAddrK + j * 16 * SROWFW * 4 + ks * 32);
                mma_f16(cs[0][2*j],   af[0][0], af[0][1], af[0][2], af[0][3], bb[0], bb[1]);
                mma_f16(cs[1][2*j],   af[1][0], af[1][1], af[1][2], af[1][3], bb[0], bb[1]);
                mma_f16(cs[0][2*j+1], af[0][0], af[0][1], af[0][2], af[0][3], bb[2], bb[3]);
                mma_f16(cs[1][2*j+1], af[1][0], af[1][1], af[1][2], af[1][3], bb[2], bb[3]);
            }
        }

        // ---- online softmax
        #pragma unroll
        for (int mt = 0; mt < 2; mt++)
            #pragma unroll
            for (int hf = 0; hf < 2; hf++) {
                float mx = -1e30f;
                #pragma unroll
                for (int nt = 0; nt < 8; nt++)
                    mx = fmaxf(mx, fmaxf(cs[mt][nt][hf*2], cs[mt][nt][hf*2+1]));
                mx = fmaxf(mx, __shfl_xor_sync(0xffffffffu, mx, 1));
                mx = fmaxf(mx, __shfl_xor_sync(0xffffffffu, mx, 2));
                if ((lane & 3) == 0) redmax[wn * 128 + myrow[mt][hf]] = mx;
            }
        __syncthreads();   // all warps done reading K from KP

        float sc[2][2];
        #pragma unroll
        for (int mt = 0; mt < 2; mt++)
            #pragma unroll
            for (int hf = 0; hf < 2; hf++) {
                int r = myrow[mt][hf];
                float mnew = fmaxf(m_[mt][hf], fmaxf(redmax[r], redmax[128 + r]));
                sc[mt][hf] = __expf(m_[mt][hf] - mnew);
                m_[mt][hf] = mnew;
            }

        // exp, partial sums, write P (fp16) into KP
        #pragma unroll
        for (int mt = 0; mt < 2; mt++)
            #pragma unroll
            for (int hf = 0; hf < 2; hf++) {
                int r = myrow[mt][hf];
                float mnew = m_[mt][hf];
                float sum = 0.f;
                __half2* prow = (__half2*)KPw + r * SROWFW + wn * 32 + (lane & 3);
                #pragma unroll
                for (int nt = 0; nt < 8; nt++) {
                    float p0 = __expf(cs[mt][nt][hf*2+0] - mnew);
                    float p1 = __expf(cs[mt][nt][hf*2+1] - mnew);
                    sum += p0 + p1;
                    prow[nt * 4] = __floats2half2_rn(p0, p1);
                }
                sum += __shfl_xor_sync(0xffffffffu, sum, 1);
                sum += __shfl_xor_sync(0xffffffffu, sum, 2);
                if ((lane & 3) == 0) redsum[wn * 128 + r] = sum;
            }
        CP_WAIT0();
        __syncthreads();   // P + redsum + V visible

        #pragma unroll
        for (int mt = 0; mt < 2; mt++)
            #pragma unroll
            for (int hf = 0; hf < 2; hf++) {
                int r = myrow[mt][hf];
                l_[mt][hf] = l_[mt][hf] * sc[mt][hf] + redsum[r] + redsum[128 + r];
                #pragma unroll
                for (int nt = 0; nt < 8; nt++) {
                    co[mt][nt][hf*2+0] *= sc[mt][hf];
                    co[mt][nt][hf*2+1] *= sc[mt][hf];
                }
            }

        // ---- O += P @ V^T
        #pragma unroll
        for (int ks = 0; ks < 8; ks++) {
            uint32_t af[2][4];
            ldsm_x4(af[0], aAddrP + ks * 32);
            ldsm_x4(af[1], aAddrP + 16 * SROWFW * 4 + ks * 32);
            #pragma unroll
            for (int j = 0; j < 4; j++) {
                uint32_t bb[4];
                ldsm_x4(bb, bAddrV + j * 16 * SROWFW * 4 + ks * 32);
                mma_f16(co[0][2*j],   af[0][0], af[0][1], af[0][2], af[0][3], bb[0], bb[1]);
                mma_f16(co[1][2*j],   af[1][0], af[1][1], af[1][2], af[1][3], bb[0], bb[1]);
                mma_f16(co[0][2*j+1], af[0][0], af[0][1], af[0][2], af[0][3], bb[2], bb[3]);
                mma_f16(co[1][2*j+1], af[1][0], af[1][1], af[1][2], af[1][3], bb[2], bb[3]);
            }
        }
        __syncthreads();   // PV done before next chunk overwrites KP/Vs
    }

    // ---- epilogue: normalize, write g_attn (fp16)
    #pragma unroll
    for (int mt = 0; mt < 2; mt++)
        #pragma unroll
        for (int hf = 0; hf < 2; hf++) {
            int r = myrow[mt][hf];
            float inv = 1.f / l_[mt][hf];
            __half2* dst = (__half2*)(g_attn + ((size_t)b * SEQ + s0 + r) * D_IN
                                      + h * HD + wn * 64 + (lane & 3) * 2);
            #pragma unroll
            for (int nt = 0; nt < 8; nt++)
                dst[nt * 4] = __floats2half2_rn(co[mt][nt][hf*2+0] * inv,
                                                co[mt][nt][hf*2+1] * inv);
        }
}

// ---------------------------------------------------------------- prep kernels

__global__ void cvt_x_kernel(const float* __restrict__ x)
{
    int i = blockIdx.x * blockDim.x + threadIdx.x;
    float4 v = ((const float4*)x)[i];
    ((__half2*)g_xc)[i * 2 + 0] = __floats2half2_rn(v.x, v.y);
    ((__half2*)g_xc)[i * 2 + 1] = __floats2half2_rn(v.z, v.w);
}

__global__ void transpose_kernel(const float* __restrict__ src, __half* __restrict__ dst,
                                 int K, int N)
{
    __shared__ float t[32][33];
    int n0 = blockIdx.x * 32, k0 = blockIdx.y * 32;
    int tx = threadIdx.x, ty = threadIdx.y;
    #pragma unroll
    for (int j = 0; j < 32; j += 8)
        t[ty + j][tx] = src[(size_t)(k0 + ty + j) * N + n0 + tx];
    __syncthreads();
    #pragma unroll
    for (int j = 0; j < 32; j += 8)
        dst[(size_t)(n0 + ty + j) * K + k0 + tx] = __float2half(t[tx][ty + j]);
}

__global__ void bias_combine_kernel(const float* __restrict__ bq,
                                    const float* __restrict__ bk,
                                    const float* __restrict__ bv)
{
    int i = blockIdx.x * blockDim.x + threadIdx.x;
    if (i >= QKV_N) return;
    float v;
    if (i < 2048) v = bq[i];
    else if (i < 2304) v = bk[i - 2048];
    else v = bv[i - 2304];
    g_bias[i] = v;
}

__global__ void rope_q_kernel()
{
    int idx = blockIdx.x * blockDim.x + threadIdx.x;
    int j = idx & 63;
    int h = (idx >> 6) & 15;
    int m = idx >> 10;
    const float* src = g_qkv + (size_t)m * QKV_N + h * HD;
    float x1 = src[j], x2 = src[j + 64];
    int s = m & 511, b = m >> 9;
    float pos = (float)(CACHE + s);
    float freq = pos * expf(-(float)j * (9.210340371976184f / 64.f));
    float sn, cs; sincosf(freq, &sn, &cs);
    const float SCALE = 0.08838834764831845f;
    __half* dst = g_q + (((size_t)b * HEADS + h) * SEQ + s) * HD;
    dst[j]      = __float2half((x1 * cs - x2 * sn) * SCALE);
    dst[j + 64] = __float2half((x2 * cs + x1 * sn) * SCALE);
}

// rope k + v copy + transposed-V write (vt_new fused in)
__global__ void rope_kv_kernel(float* __restrict__ out_k, float* __restrict__ out_v)
{
    int idx = blockIdx.x * blockDim.x + threadIdx.x;
    int j = idx & 63;
    int g = (idx >> 6) & 1;
    int m = idx >> 7;
    const float* ksrc = g_qkv + (size_t)m * QKV_N + 2048 + g * HD;
    const float* vsrc = g_qkv + (size_t)m * QKV_N + 2304 + g * HD;
    float x1 = ksrc[j], x2 = ksrc[j + 64];
    int s = m & 511, b = m >> 9;
    float pos = (float)(CACHE + s);
    float freq = pos * expf(-(float)j * (9.210340371976184f / 64.f));
    float sn, cs; sincosf(freq, &sn, &cs);
    float k1 = x1 * cs - x2 * sn;
    float k2 = x2 * cs + x1 * sn;
    size_t base = (((size_t)b * T_TOT + CACHE + s) * GROUPS + g) * HD;
    out_k[base + j]      = k1;
    out_k[base + j + 64] = k2;
    g_kc[base + j]       = __float2half(k1);
    g_kc[base + j + 64]  = __float2half(k2);
    float v1 = vsrc[j], v2 = vsrc[j + 64];
    out_v[base + j]      = v1;
    out_v[base + j + 64] = v2;
    int bg = b * 2 + g;
    g_vT[(size_t)bg * HD * T_TOT + (size_t)j * T_TOT + CACHE + s]        = __float2half(v1);
    g_vT[(size_t)bg * HD * T_TOT + (size_t)(j + 64) * T_TOT + CACHE + s] = __float2half(v2);
}

// prev cache copy + fp16 K cache + transposed-V history (vt_prev fused in)
__global__ void copy_prev_kernel(const float* __restrict__ prev_k,
                                 const float* __restrict__ prev_v,
                                 float* __restrict__ out_k,
                                 float* __restrict__ out_v)
{
    int idx = blockIdx.x * blockDim.x + threadIdx.x;
    if (idx >= BATCH * CACHE * GROUPS * HD) return;
    int b = idx >> 16;
    int r = idx & 65535;                 // ((t*GROUPS+g)*HD + hd)
    float kv = prev_k[idx];
    float vv = prev_v[idx];
    out_k[(size_t)b * (T_TOT * GROUPS * HD) + r] = kv;
    g_kc[(size_t)b * (T_TOT * GROUPS * HD) + r]  = __float2half(kv);
    out_v[(size_t)b * (T_TOT * GROUPS * HD) + r] = vv;
    int t = r >> 8;                      // r = t*256 + g*128 + hd  (FIX: was >>9)
    int g = (r >> 7) & 1;
    int hd = r & 127;
    g_vT[(size_t)(b * 2 + g) * HD * T_TOT + (size_t)hd * T_TOT + t] = __float2half(vv);
}

// ---------------------------------------------------------------- launcher
extern "C" void kernel_launch(void* const* d_in, const int* in_sizes, int n_in,
                              void* d_out, int out_size)
{
    const float* x      = (const float*)d_in[0];
    const float* prev_k = (const float*)d_in[1];
    const float* prev_v = (const float*)d_in[2];
    const float* Wq     = (const float*)d_in[3];
    const float* bq     = (const float*)d_in[4];
    const float* Wk     = (const float*)d_in[5];
    const float* bk     = (const float*)d_in[6];
    const float* Wv     = (const float*)d_in[7];
    const float* bv     = (const float*)d_in[8];
    const float* Wo     = (const float*)d_in[9];
    const float* bo     = (const float*)d_in[10];

    float* out_o = (float*)d_out;
    float* out_k = out_o + OUT_O_SIZE;
    float* out_v = out_k + OUT_K_SIZE;

    static bool attr_set = false;
    if (!attr_set) {
        cudaFuncSetAttribute(qkv_gemm_kernel,     cudaFuncAttributeMaxDynamicSharedMemorySize, GEMM_SMEM_BYTES);
        cudaFuncSetAttribute(outproj_gemm_kernel, cudaFuncAttributeMaxDynamicSharedMemorySize, GEMM_SMEM_BYTES);
        cudaFuncSetAttribute(flash_attn_kernel,   cudaFuncAttributeMaxDynamicSharedMemorySize, FLASH_SMEM_BYTES);
        attr_set = true;
    }

    // 0. Operand preparation
    cvt_x_kernel<<<(M_ROWS * D_IN / 4) / 256, 256>>>(x);
    {
        __half* wT = nullptr; cudaGetSymbolAddress((void**)&wT, g_wT);
        __half* woT = nullptr; cudaGetSymbolAddress((void**)&woT, g_woT);
        dim3 blk(32, 8);
        transpose_kernel<<<dim3(64, 64), blk>>>(Wq, wT, D_IN, D_IN);
        transpose_kernel<<<dim3(8, 64), blk>>>(Wk, wT + 2048 * D_IN, D_IN, 256);
        transpose_kernel<<<dim3(8, 64), blk>>>(Wv, wT + 2304 * D_IN, D_IN, 256);
        transpose_kernel<<<dim3(64, 64), blk>>>(Wo, woT, D_IN, D_IN);
        bias_combine_kernel<<<(QKV_N + 255) / 256, 256>>>(bq, bk, bv);
    }

    // 1. kv-cache history (fused: out_k/out_v + fp16 K cache + transposed V)
    copy_prev_kernel<<<2048, 256>>>(prev_k, prev_v, out_k, out_v);

    // 2. QKV projection
    qkv_gemm_kernel<<<dim3(M_ROWS / 128, QKV_N / 128), 256, GEMM_SMEM_BYTES>>>();

    // 3. RoPE q / RoPE k + v copy + transposed V (fused)
    rope_q_kernel<<<M_ROWS * HEADS * 64 / 256, 256>>>();
    rope_kv_kernel<<<M_ROWS * GROUPS * 64 / 256, 256>>>(out_k, out_v);

    // 4. Fused flash attention
    flash_attn_kernel<<<dim3(SEQ / 128, BATCH * HEADS), 256, FLASH_SMEM_BYTES>>>();

    // 5. Output projection
    outproj_gemm_kernel<<<dim3(M_ROWS / 128, D_IN / 128), 256, GEMM_SMEM_BYTES>>>(bo, out_o);
}